// round 1
// baseline (speedup 1.0000x reference)
#include <cuda_runtime.h>
#include <math.h>

namespace {
constexpr int kS = 2048, kB = 2, kD = 1024, kH = 16, kDh = 64;
constexpr int kRows = kS * kB;            // 4096
constexpr float kScale = 0.125f;          // 1/sqrt(64)
constexpr float kEps = 1e-5f;
}

// ------------------------- scratch (static device memory) -------------------
__device__ float g_xn[kRows * kD];                 // normed input [row=i*B+b][D]
__device__ float g_q[kB * kH * kS * kDh];          // q + rw,  [b][h][s][d]
__device__ float g_k[kB * kH * kS * kDh];          // [b][h][s][d]
__device__ float g_v[kB * kH * kS * kDh];          // [b][h][s][d]
__device__ float g_av[kRows * kD];                 // attn output [row][h*64+d]
__device__ float g_rk0[kH * kDh];                  // r @ Wr
__device__ float g_c[kS * kB * kH];                // BD constants c[i,b,h]

// ------------------------------ LayerNorm -----------------------------------
__global__ void ln_kernel(const float* __restrict__ x,
                          const float* __restrict__ gamma,
                          const float* __restrict__ beta) {
    int row = blockIdx.x;
    int t = threadIdx.x;
    const float4 v = reinterpret_cast<const float4*>(x + (size_t)row * kD)[t];
    float s1 = v.x + v.y + v.z + v.w;
    float s2 = v.x*v.x + v.y*v.y + v.z*v.z + v.w*v.w;
    #pragma unroll
    for (int o = 16; o; o >>= 1) {
        s1 += __shfl_xor_sync(~0u, s1, o);
        s2 += __shfl_xor_sync(~0u, s2, o);
    }
    __shared__ float sm1[8], sm2[8];
    int w = t >> 5, lane = t & 31;
    if (lane == 0) { sm1[w] = s1; sm2[w] = s2; }
    __syncthreads();
    if (w == 0) {
        s1 = (lane < 8) ? sm1[lane] : 0.f;
        s2 = (lane < 8) ? sm2[lane] : 0.f;
        #pragma unroll
        for (int o = 4; o; o >>= 1) {
            s1 += __shfl_xor_sync(~0u, s1, o);
            s2 += __shfl_xor_sync(~0u, s2, o);
        }
        if (lane == 0) { sm1[0] = s1; sm2[0] = s2; }
    }
    __syncthreads();
    float mu = sm1[0] * (1.f / kD);
    float var = sm2[0] * (1.f / kD) - mu * mu;
    float rstd = rsqrtf(var + kEps);
    const float4 gv = reinterpret_cast<const float4*>(gamma)[t];
    const float4 bv = reinterpret_cast<const float4*>(beta)[t];
    float4 o;
    o.x = (v.x - mu) * rstd * gv.x + bv.x;
    o.y = (v.y - mu) * rstd * gv.y + bv.y;
    o.z = (v.z - mu) * rstd * gv.z + bv.z;
    o.w = (v.w - mu) * rstd * gv.w + bv.w;
    reinterpret_cast<float4*>(g_xn + (size_t)row * kD)[t] = o;
}

// ----------------------------- rk0 = r @ Wr ----------------------------------
__global__ void rk0_kernel(const float* __restrict__ r, const float* __restrict__ Wr) {
    int col = blockIdx.x * blockDim.x + threadIdx.x;   // < 1024
    float s = 0.f;
    for (int d = 0; d < kD; d++) s += r[d] * Wr[(size_t)d * kD + col];
    g_rk0[col] = s;
}

// ------------------------------ QKV GEMM -------------------------------------
// C[4096,3072] = g_xn @ Wqkv ; scatter into g_q(+rw)/g_k/g_v with [b][h][s][d]
__global__ __launch_bounds__(256) void gemm_qkv_kernel(const float* __restrict__ Wqkv,
                                                       const float* __restrict__ rw) {
    constexpr int N = 3 * kD, K = kD;
    __shared__ float As[16][128];    // transposed: As[k][m]
    __shared__ float Bs[16][128];
    int tid = threadIdx.x;
    int m0 = blockIdx.y * 128, n0 = blockIdx.x * 128;
    int tr = tid >> 4, tc = tid & 15;
    float acc[8][8] = {};
    for (int k0 = 0; k0 < K; k0 += 16) {
        #pragma unroll
        for (int t = 0; t < 2; t++) {
            int idx = tid + t * 256;
            int row = idx >> 2, kq = (idx & 3) * 4;
            float4 a = *reinterpret_cast<const float4*>(&g_xn[(size_t)(m0 + row) * K + k0 + kq]);
            As[kq + 0][row] = a.x; As[kq + 1][row] = a.y;
            As[kq + 2][row] = a.z; As[kq + 3][row] = a.w;
        }
        #pragma unroll
        for (int t = 0; t < 2; t++) {
            int idx = tid + t * 256;
            int kk = idx >> 5, c4 = (idx & 31) * 4;
            *reinterpret_cast<float4*>(&Bs[kk][c4]) =
                *reinterpret_cast<const float4*>(&Wqkv[(size_t)(k0 + kk) * N + n0 + c4]);
        }
        __syncthreads();
        #pragma unroll
        for (int kk = 0; kk < 16; kk++) {
            float af[8], bf[8];
            *(float4*)&af[0] = *(float4*)&As[kk][tr * 8];
            *(float4*)&af[4] = *(float4*)&As[kk][tr * 8 + 4];
            *(float4*)&bf[0] = *(float4*)&Bs[kk][tc * 8];
            *(float4*)&bf[4] = *(float4*)&Bs[kk][tc * 8 + 4];
            #pragma unroll
            for (int i = 0; i < 8; i++)
                #pragma unroll
                for (int j = 0; j < 8; j++) acc[i][j] += af[i] * bf[j];
        }
        __syncthreads();
    }
    #pragma unroll
    for (int i = 0; i < 8; i++) {
        int row = m0 + tr * 8 + i;
        int si = row >> 1, bb = row & 1;
        #pragma unroll
        for (int j = 0; j < 8; j++) {
            int col = n0 + tc * 8 + j;
            int part = col >> 10, rem = col & 1023;
            int h = rem >> 6, d = rem & 63;
            size_t di = (((size_t)(bb * kH + h)) * kS + si) * kDh + d;
            float v = acc[i][j];
            if (part == 0)       g_q[di] = v + rw[rem];
            else if (part == 1)  g_k[di] = v;
            else                 g_v[di] = v;
        }
    }
}

// ----------------- BD constants: c[i,b,h] = (q + rr)·rk0 ---------------------
// g_q already holds q+rw, so use (g_q - rw + rr)·rk0.
__global__ void cbd_kernel(const float* __restrict__ rw, const float* __restrict__ rr) {
    int warp = blockIdx.x * 8 + (threadIdx.x >> 5);
    int lane = threadIdx.x & 31;
    int h = warp & 15, bb = (warp >> 4) & 1, i = warp >> 5;
    float s = 0.f;
    #pragma unroll
    for (int t = 0; t < 2; t++) {
        int d = lane + t * 32;
        size_t qi = (((size_t)(bb * kH + h)) * kS + i) * kDh + d;
        int hd = h * kDh + d;
        s += (g_q[qi] - rw[hd] + rr[hd]) * g_rk0[hd];
    }
    #pragma unroll
    for (int o = 16; o; o >>= 1) s += __shfl_xor_sync(~0u, s, o);
    if (lane == 0) g_c[((size_t)i * kB + bb) * kH + h] = s;
}

// ------------------------- Flash attention (fp32) ----------------------------
// Per block: one (b,h), 64 query rows. Online softmax over 32 key tiles of 64.
// BD term: logit[i,j] += c[i] if j<=i ; 0 if j==i+1 ; c[i+1] if j>=i+2.
__global__ __launch_bounds__(256) void flash_kernel() {
    __shared__ float Qs[64][64];     // [row][d]
    __shared__ float KVs[64][64];    // K: [d][j] (transposed) then V: [j][d]
    __shared__ float Ps[64][64];     // probabilities [row][j]
    int b = blockIdx.z, h = blockIdx.y;
    int i0 = blockIdx.x * 64;
    int tid = threadIdx.x;
    int ty = tid >> 4, tx = tid & 15;
    size_t base = ((size_t)(b * kH + h)) * kS * kDh;

    #pragma unroll
    for (int t = 0; t < 4; t++) {
        int idx = tid + t * 256;
        int r = idx >> 4, d4 = (idx & 15) * 4;
        *(float4*)&Qs[r][d4] = *(const float4*)&g_q[base + (size_t)(i0 + r) * 64 + d4];
    }

    float m[4], l[4], acc[4][4];
    #pragma unroll
    for (int i = 0; i < 4; i++) {
        m[i] = -1e30f; l[i] = 0.f;
        #pragma unroll
        for (int j = 0; j < 4; j++) acc[i][j] = 0.f;
    }
    float cI[4], cI1[4];
    #pragma unroll
    for (int ri = 0; ri < 4; ri++) {
        int gi = i0 + ty * 4 + ri;
        cI[ri]  = g_c[((size_t)gi * kB + b) * kH + h];
        cI1[ri] = (gi + 1 < kS) ? g_c[((size_t)(gi + 1) * kB + b) * kH + h] : 0.f;
    }

    for (int j0 = 0; j0 < kS; j0 += 64) {
        __syncthreads();   // previous iteration's PV reads done
        // Load K tile transposed: KVs[d][j]
        #pragma unroll
        for (int t = 0; t < 4; t++) {
            int idx = tid + t * 256;
            int jj = idx >> 4, d4 = (idx & 15) * 4;
            float4 kv = *(const float4*)&g_k[base + (size_t)(j0 + jj) * 64 + d4];
            KVs[d4 + 0][jj] = kv.x; KVs[d4 + 1][jj] = kv.y;
            KVs[d4 + 2][jj] = kv.z; KVs[d4 + 3][jj] = kv.w;
        }
        __syncthreads();

        // S = Q @ K^T  (s[ri][cj], rows ty*4+ri, key cols tx*4+cj)
        float s[4][4] = {};
        #pragma unroll
        for (int kk = 0; kk < 64; kk += 4) {
            float qf[4][4], kf[4][4];
            #pragma unroll
            for (int ri = 0; ri < 4; ri++)
                *(float4*)qf[ri] = *(float4*)&Qs[ty * 4 + ri][kk];
            #pragma unroll
            for (int u = 0; u < 4; u++)
                *(float4*)kf[u] = *(float4*)&KVs[kk + u][tx * 4];
            #pragma unroll
            for (int ri = 0; ri < 4; ri++)
                #pragma unroll
                for (int cj = 0; cj < 4; cj++)
                    s[ri][cj] += qf[ri][0] * kf[0][cj] + qf[ri][1] * kf[1][cj]
                               + qf[ri][2] * kf[2][cj] + qf[ri][3] * kf[3][cj];
        }

        // BD + scale + online softmax
        float alpha[4];
        #pragma unroll
        for (int ri = 0; ri < 4; ri++) {
            int gi = i0 + ty * 4 + ri;
            float lv[4], rowmax = -1e30f;
            #pragma unroll
            for (int cj = 0; cj < 4; cj++) {
                int gj = j0 + tx * 4 + cj;
                float bd = (gj <= gi) ? cI[ri] : ((gj == gi + 1) ? 0.f : cI1[ri]);
                lv[cj] = (s[ri][cj] + bd) * kScale;
                rowmax = fmaxf(rowmax, lv[cj]);
            }
            #pragma unroll
            for (int o = 8; o; o >>= 1) rowmax = fmaxf(rowmax, __shfl_xor_sync(~0u, rowmax, o));
            float mn = fmaxf(m[ri], rowmax);
            alpha[ri] = __expf(m[ri] - mn);
            float rs = 0.f;
            #pragma unroll
            for (int cj = 0; cj < 4; cj++) {
                float p = __expf(lv[cj] - mn);
                Ps[ty * 4 + ri][tx * 4 + cj] = p;
                rs += p;
            }
            #pragma unroll
            for (int o = 8; o; o >>= 1) rs += __shfl_xor_sync(~0u, rs, o);
            l[ri] = l[ri] * alpha[ri] + rs;
            m[ri] = mn;
            #pragma unroll
            for (int cj = 0; cj < 4; cj++) acc[ri][cj] *= alpha[ri];
        }
        __syncthreads();   // Ps written, K reads done

        // Load V tile (normal layout): KVs[j][d]
        #pragma unroll
        for (int t = 0; t < 4; t++) {
            int idx = tid + t * 256;
            int jj = idx >> 4, d4 = (idx & 15) * 4;
            *(float4*)&KVs[jj][d4] = *(const float4*)&g_v[base + (size_t)(j0 + jj) * 64 + d4];
        }
        __syncthreads();

        // O += P @ V
        #pragma unroll
        for (int kk = 0; kk < 64; kk += 4) {
            float pf[4][4], vf[4][4];
            #pragma unroll
            for (int ri = 0; ri < 4; ri++)
                *(float4*)pf[ri] = *(float4*)&Ps[ty * 4 + ri][kk];
            #pragma unroll
            for (int u = 0; u < 4; u++)
                *(float4*)vf[u] = *(float4*)&KVs[kk + u][tx * 4];
            #pragma unroll
            for (int ri = 0; ri < 4; ri++)
                #pragma unroll
                for (int cj = 0; cj < 4; cj++)
                    acc[ri][cj] += pf[ri][0] * vf[0][cj] + pf[ri][1] * vf[1][cj]
                                 + pf[ri][2] * vf[2][cj] + pf[ri][3] * vf[3][cj];
        }
    }

    #pragma unroll
    for (int ri = 0; ri < 4; ri++) {
        int gi = i0 + ty * 4 + ri;
        float inv = 1.f / l[ri];
        #pragma unroll
        for (int cj = 0; cj < 4; cj++)
            g_av[((size_t)gi * kB + b) * kD + h * kDh + tx * 4 + cj] = acc[ri][cj] * inv;
    }
}

// ---------------------- Output GEMM + residual -------------------------------
// out[4096,1024] = g_xn + g_av @ Wo
__global__ __launch_bounds__(256) void gemm_out_kernel(const float* __restrict__ Wo,
                                                       float* __restrict__ out) {
    constexpr int N = kD, K = kD;
    __shared__ float As[16][128];
    __shared__ float Bs[16][128];
    int tid = threadIdx.x;
    int m0 = blockIdx.y * 128, n0 = blockIdx.x * 128;
    int tr = tid >> 4, tc = tid & 15;
    float acc[8][8] = {};
    for (int k0 = 0; k0 < K; k0 += 16) {
        #pragma unroll
        for (int t = 0; t < 2; t++) {
            int idx = tid + t * 256;
            int row = idx >> 2, kq = (idx & 3) * 4;
            float4 a = *reinterpret_cast<const float4*>(&g_av[(size_t)(m0 + row) * K + k0 + kq]);
            As[kq + 0][row] = a.x; As[kq + 1][row] = a.y;
            As[kq + 2][row] = a.z; As[kq + 3][row] = a.w;
        }
        #pragma unroll
        for (int t = 0; t < 2; t++) {
            int idx = tid + t * 256;
            int kk = idx >> 5, c4 = (idx & 31) * 4;
            *reinterpret_cast<float4*>(&Bs[kk][c4]) =
                *reinterpret_cast<const float4*>(&Wo[(size_t)(k0 + kk) * N + n0 + c4]);
        }
        __syncthreads();
        #pragma unroll
        for (int kk = 0; kk < 16; kk++) {
            float af[8], bf[8];
            *(float4*)&af[0] = *(float4*)&As[kk][tr * 8];
            *(float4*)&af[4] = *(float4*)&As[kk][tr * 8 + 4];
            *(float4*)&bf[0] = *(float4*)&Bs[kk][tc * 8];
            *(float4*)&bf[4] = *(float4*)&Bs[kk][tc * 8 + 4];
            #pragma unroll
            for (int i = 0; i < 8; i++)
                #pragma unroll
                for (int j = 0; j < 8; j++) acc[i][j] += af[i] * bf[j];
        }
        __syncthreads();
    }
    #pragma unroll
    for (int i = 0; i < 8; i++) {
        int row = m0 + tr * 8 + i;
        #pragma unroll
        for (int j = 0; j < 8; j++) {
            int col = n0 + tc * 8 + j;
            size_t oi = (size_t)row * N + col;
            out[oi] = acc[i][j] + g_xn[oi];
        }
    }
}

// --------------------------------- launch ------------------------------------
extern "C" void kernel_launch(void* const* d_in, const int* in_sizes, int n_in,
                              void* d_out, int out_size) {
    const float* x    = (const float*)d_in[0];
    const float* r    = (const float*)d_in[1];
    const float* rw   = (const float*)d_in[2];
    const float* rr   = (const float*)d_in[3];
    const float* ln_g = (const float*)d_in[4];
    const float* ln_b = (const float*)d_in[5];
    const float* Wqkv = (const float*)d_in[6];
    const float* Wr   = (const float*)d_in[7];
    const float* Wo   = (const float*)d_in[8];
    float* out = (float*)d_out;

    ln_kernel<<<kRows, 256>>>(x, ln_g, ln_b);
    rk0_kernel<<<4, 256>>>(r, Wr);
    gemm_qkv_kernel<<<dim3(3 * kD / 128, kRows / 128), 256>>>(Wqkv, rw);
    cbd_kernel<<<kS * kB * kH / 8, 256>>>(rw, rr);
    flash_kernel<<<dim3(kS / 64, kH, kB), 256>>>();
    gemm_out_kernel<<<dim3(kD / 128, kRows / 128), 256>>>(Wo, out);
}

// round 7
// speedup vs baseline: 4.4625x; 4.4625x over previous
#include <cuda_runtime.h>
#include <cuda_fp16.h>
#include <math.h>

namespace {
constexpr int kS = 2048, kB = 2, kD = 1024, kH = 16, kDh = 64;
constexpr int kRows = kS * kB;            // 4096
constexpr float kScale = 0.125f;          // 1/sqrt(64)
constexpr float kEps = 1e-5f;
}

// ------------------------- scratch (static device memory) -------------------
// NOTE: these symbols are ONLY referenced inside device code — never passed
// as kernel arguments from host (host-side symbol decay gives the host shadow
// address, which ATS happily dereferences into the wrong memory).
__device__ float  g_xn[kRows * kD];                // normed input fp32 (residual)
__device__ __half g_xn_h[kRows * kD];              // normed input fp16 (GEMM A)
__device__ __half g_wqkv_t[3 * kD * kD];           // Wqkv^T  [n=3072][k=1024]
__device__ __half g_wo_t[kD * kD];                 // Wo^T    [n=1024][k=1024]
__device__ __half g_q[kB * kH * kS * kDh];         // q + rw  [b][h][s][d]
__device__ __half g_k[kB * kH * kS * kDh];         // [b][h][s][d]
__device__ __half g_vt[kB * kH * kDh * kS];        // V^T [b][h][d][s]
__device__ __half g_av[kRows * kD];                // attn out fp16 [row][h*64+d]
__device__ float  g_rk0[kD];                       // r @ Wr
__device__ float  g_c[kS * kB * kH];               // BD constants c[i,b,h]

// ------------------------------ mma helper -----------------------------------
__device__ __forceinline__ void mma16816(float* c, const unsigned* a, const unsigned* b) {
    asm volatile(
        "mma.sync.aligned.m16n8k16.row.col.f32.f16.f16.f32 "
        "{%0,%1,%2,%3},{%4,%5,%6,%7},{%8,%9},{%0,%1,%2,%3};\n"
        : "+f"(c[0]), "+f"(c[1]), "+f"(c[2]), "+f"(c[3])
        : "r"(a[0]), "r"(a[1]), "r"(a[2]), "r"(a[3]), "r"(b[0]), "r"(b[1]));
}

// ------------------------------ LayerNorm -----------------------------------
__global__ void ln_kernel(const float* __restrict__ x,
                          const float* __restrict__ gamma,
                          const float* __restrict__ beta) {
    int row = blockIdx.x;
    int t = threadIdx.x;
    const float4 v = reinterpret_cast<const float4*>(x + (size_t)row * kD)[t];
    float s1 = v.x + v.y + v.z + v.w;
    float s2 = v.x*v.x + v.y*v.y + v.z*v.z + v.w*v.w;
    #pragma unroll
    for (int o = 16; o; o >>= 1) {
        s1 += __shfl_xor_sync(~0u, s1, o);
        s2 += __shfl_xor_sync(~0u, s2, o);
    }
    __shared__ float sm1[8], sm2[8];
    int w = t >> 5, lane = t & 31;
    if (lane == 0) { sm1[w] = s1; sm2[w] = s2; }
    __syncthreads();
    if (w == 0) {
        s1 = (lane < 8) ? sm1[lane] : 0.f;
        s2 = (lane < 8) ? sm2[lane] : 0.f;
        #pragma unroll
        for (int o = 4; o; o >>= 1) {
            s1 += __shfl_xor_sync(~0u, s1, o);
            s2 += __shfl_xor_sync(~0u, s2, o);
        }
        if (lane == 0) { sm1[0] = s1; sm2[0] = s2; }
    }
    __syncthreads();
    float mu = sm1[0] * (1.f / kD);
    float var = sm2[0] * (1.f / kD) - mu * mu;
    float rstd = rsqrtf(var + kEps);
    const float4 gv = reinterpret_cast<const float4*>(gamma)[t];
    const float4 bv = reinterpret_cast<const float4*>(beta)[t];
    float4 o;
    o.x = (v.x - mu) * rstd * gv.x + bv.x;
    o.y = (v.y - mu) * rstd * gv.y + bv.y;
    o.z = (v.z - mu) * rstd * gv.z + bv.z;
    o.w = (v.w - mu) * rstd * gv.w + bv.w;
    reinterpret_cast<float4*>(g_xn + (size_t)row * kD)[t] = o;
    *reinterpret_cast<__half2*>(&g_xn_h[(size_t)row * kD + t * 4])     = __floats2half2_rn(o.x, o.y);
    *reinterpret_cast<__half2*>(&g_xn_h[(size_t)row * kD + t * 4 + 2]) = __floats2half2_rn(o.z, o.w);
}

// --------------- weight transpose + fp32 -> fp16 conversion ------------------
// WHICH=0: g_wqkv_t[n][k] = Wqkv[k][n] (N=3072); WHICH=1: g_wo_t = Wo^T (N=1024)
template <int WHICH>
__global__ void convw_kernel(const float* __restrict__ src) {
    constexpr int K = kD;
    constexpr int N = (WHICH == 0) ? 3 * kD : kD;
    __half* dst = (WHICH == 0) ? g_wqkv_t : g_wo_t;   // resolved in device code
    __shared__ float tile[32][33];
    int n0 = blockIdx.x * 32, k0 = blockIdx.y * 32;
    int tx = threadIdx.x, ty = threadIdx.y;
    #pragma unroll
    for (int i = 0; i < 32; i += 8)
        tile[ty + i][tx] = src[(size_t)(k0 + ty + i) * N + n0 + tx];
    __syncthreads();
    #pragma unroll
    for (int i = 0; i < 32; i += 8)
        dst[(size_t)(n0 + ty + i) * K + k0 + tx] = __float2half(tile[tx][ty + i]);
}

// ----------------------------- rk0 = r @ Wr ----------------------------------
__global__ void rk0_kernel(const float* __restrict__ r, const float* __restrict__ Wr) {
    int col = blockIdx.x * blockDim.x + threadIdx.x;   // < 1024
    float s = 0.f;
    for (int d = 0; d < kD; d++) s += r[d] * Wr[(size_t)d * kD + col];
    g_rk0[col] = s;
}

// ------------------------------ QKV GEMM (fp16 mma) --------------------------
// C[4096,3072] = xn_h @ Wqkv ; scatter fp16 into g_q(+rw)/g_k/g_vt
__global__ __launch_bounds__(256) void gemm_qkv_kernel(const float* __restrict__ rw) {
    __shared__ __half As[128][40];
    __shared__ __half Bs[128][40];
    int tid = threadIdx.x, lane = tid & 31, w = tid >> 5;
    int gid = lane >> 2, tig = lane & 3;
    int m0 = blockIdx.y * 128, n0 = blockIdx.x * 128;
    int wm = w >> 2, wn = w & 3;
    float acc[4][4][4] = {};
    for (int k0 = 0; k0 < kD; k0 += 32) {
        #pragma unroll
        for (int t = 0; t < 2; t++) {
            int idx = tid + t * 256;
            int r = idx >> 2, c = (idx & 3) * 8;
            *(float4*)&As[r][c] = *(const float4*)&g_xn_h[(size_t)(m0 + r) * kD + k0 + c];
            *(float4*)&Bs[r][c] = *(const float4*)&g_wqkv_t[(size_t)(n0 + r) * kD + k0 + c];
        }
        __syncthreads();
        #pragma unroll
        for (int kb = 0; kb < 32; kb += 16) {
            unsigned a[4][4], b[4][2];
            #pragma unroll
            for (int mi = 0; mi < 4; mi++) {
                int r = wm * 64 + mi * 16 + gid;
                a[mi][0] = *(unsigned*)&As[r][kb + tig * 2];
                a[mi][1] = *(unsigned*)&As[r + 8][kb + tig * 2];
                a[mi][2] = *(unsigned*)&As[r][kb + 8 + tig * 2];
                a[mi][3] = *(unsigned*)&As[r + 8][kb + 8 + tig * 2];
            }
            #pragma unroll
            for (int ni = 0; ni < 4; ni++) {
                int n = wn * 32 + ni * 8 + gid;
                b[ni][0] = *(unsigned*)&Bs[n][kb + tig * 2];
                b[ni][1] = *(unsigned*)&Bs[n][kb + 8 + tig * 2];
            }
            #pragma unroll
            for (int mi = 0; mi < 4; mi++)
                #pragma unroll
                for (int ni = 0; ni < 4; ni++)
                    mma16816(acc[mi][ni], a[mi], b[ni]);
        }
        __syncthreads();
    }
    // epilogue: scatter to q/k/vt
    #pragma unroll
    for (int mi = 0; mi < 4; mi++) {
        int r0e = m0 + wm * 64 + mi * 16 + gid, r1e = r0e + 8;
        int s0 = r0e >> 1, b0e = r0e & 1;
        int s1 = r1e >> 1, b1e = r1e & 1;
        #pragma unroll
        for (int ni = 0; ni < 4; ni++) {
            int c0 = n0 + wn * 32 + ni * 8 + tig * 2;
            int part = c0 >> 10, rem = c0 & 1023, hh = rem >> 6, d = rem & 63;
            float v00 = acc[mi][ni][0], v01 = acc[mi][ni][1];
            float v10 = acc[mi][ni][2], v11 = acc[mi][ni][3];
            if (part == 0) {
                float w0 = rw[rem], w1 = rw[rem + 1];
                *(__half2*)&g_q[(((size_t)(b0e * kH + hh)) * kS + s0) * kDh + d] =
                    __floats2half2_rn(v00 + w0, v01 + w1);
                *(__half2*)&g_q[(((size_t)(b1e * kH + hh)) * kS + s1) * kDh + d] =
                    __floats2half2_rn(v10 + w0, v11 + w1);
            } else if (part == 1) {
                *(__half2*)&g_k[(((size_t)(b0e * kH + hh)) * kS + s0) * kDh + d] =
                    __floats2half2_rn(v00, v01);
                *(__half2*)&g_k[(((size_t)(b1e * kH + hh)) * kS + s1) * kDh + d] =
                    __floats2half2_rn(v10, v11);
            } else {
                size_t vb0 = (size_t)(b0e * kH + hh) * kDh;
                size_t vb1 = (size_t)(b1e * kH + hh) * kDh;
                g_vt[(vb0 + d) * kS + s0]     = __float2half(v00);
                g_vt[(vb0 + d + 1) * kS + s0] = __float2half(v01);
                g_vt[(vb1 + d) * kS + s1]     = __float2half(v10);
                g_vt[(vb1 + d + 1) * kS + s1] = __float2half(v11);
            }
        }
    }
}

// ----------------- BD constants: c[i,b,h] = (q + rr)·rk0 ---------------------
__global__ void cbd_kernel(const float* __restrict__ rw, const float* __restrict__ rr) {
    int warp = blockIdx.x * 8 + (threadIdx.x >> 5);
    int lane = threadIdx.x & 31;
    int h = warp & 15, bb = (warp >> 4) & 1, i = warp >> 5;
    float s = 0.f;
    #pragma unroll
    for (int t = 0; t < 2; t++) {
        int d = lane + t * 32;
        size_t qi = (((size_t)(bb * kH + h)) * kS + i) * kDh + d;
        int hd = h * kDh + d;
        s += (__half2float(g_q[qi]) - rw[hd] + rr[hd]) * g_rk0[hd];
    }
    #pragma unroll
    for (int o = 16; o; o >>= 1) s += __shfl_xor_sync(~0u, s, o);
    if (lane == 0) g_c[((size_t)i * kB + bb) * kH + h] = s;
}

// ------------------------- Flash attention (fp16 mma) ------------------------
// Block: 128 thr = 4 warps, one (b,h), 64 query rows (16 per warp), key tiles 64.
__global__ __launch_bounds__(128) void flash_kernel() {
    __shared__ __half Qs[64][72];
    __shared__ __half Ks[64][72];
    __shared__ __half Vt[64][72];    // [d][j]
    __shared__ __half Ps[64][72];
    int b = blockIdx.z, h = blockIdx.y, i0 = blockIdx.x * 64;
    int tid = threadIdx.x, w = tid >> 5, lane = tid & 31;
    int gid = lane >> 2, tig = lane & 3;
    size_t kbase = ((size_t)(b * kH + h)) * kS * kDh;
    size_t vbase = ((size_t)(b * kH + h)) * kDh * kS;

    #pragma unroll
    for (int t = 0; t < 4; t++) {
        int idx = tid + t * 128;
        int r = idx >> 3, c = (idx & 7) * 8;
        *(float4*)&Qs[r][c] = *(const float4*)&g_q[kbase + (size_t)(i0 + r) * kDh + c];
    }

    int r0 = i0 + w * 16 + gid, r1 = r0 + 8;
    float cA  = g_c[((size_t)r0 * kB + b) * kH + h];
    float cA1 = (r0 + 1 < kS) ? g_c[((size_t)(r0 + 1) * kB + b) * kH + h] : 0.f;
    float cB  = g_c[((size_t)r1 * kB + b) * kH + h];
    float cB1 = (r1 + 1 < kS) ? g_c[((size_t)(r1 + 1) * kB + b) * kH + h] : 0.f;

    float m0v = -1e30f, m1v = -1e30f, l0 = 0.f, l1 = 0.f;
    float o[8][4] = {};

    for (int j0 = 0; j0 < kS; j0 += 64) {
        __syncthreads();
        #pragma unroll
        for (int t = 0; t < 4; t++) {
            int idx = tid + t * 128;
            int r = idx >> 3, c = (idx & 7) * 8;
            *(float4*)&Ks[r][c] = *(const float4*)&g_k[kbase + (size_t)(j0 + r) * kDh + c];
            *(float4*)&Vt[r][c] = *(const float4*)&g_vt[vbase + (size_t)r * kS + j0 + c];
        }
        __syncthreads();

        // S = Q K^T
        float s[8][4] = {};
        #pragma unroll
        for (int kb = 0; kb < 64; kb += 16) {
            unsigned a[4];
            a[0] = *(unsigned*)&Qs[w * 16 + gid][kb + tig * 2];
            a[1] = *(unsigned*)&Qs[w * 16 + gid + 8][kb + tig * 2];
            a[2] = *(unsigned*)&Qs[w * 16 + gid][kb + 8 + tig * 2];
            a[3] = *(unsigned*)&Qs[w * 16 + gid + 8][kb + 8 + tig * 2];
            #pragma unroll
            for (int nt = 0; nt < 8; nt++) {
                unsigned bf[2];
                bf[0] = *(unsigned*)&Ks[nt * 8 + gid][kb + tig * 2];
                bf[1] = *(unsigned*)&Ks[nt * 8 + gid][kb + 8 + tig * 2];
                mma16816(s[nt], a, bf);
            }
        }

        // BD + scale + online softmax (fp32)
        float rmax0 = -1e30f, rmax1 = -1e30f;
        #pragma unroll
        for (int nt = 0; nt < 8; nt++) {
            int gj = j0 + nt * 8 + tig * 2;
            float bd00 = (gj <= r0) ? cA : ((gj == r0 + 1) ? 0.f : cA1);
            float bd01 = (gj + 1 <= r0) ? cA : ((gj + 1 == r0 + 1) ? 0.f : cA1);
            float bd10 = (gj <= r1) ? cB : ((gj == r1 + 1) ? 0.f : cB1);
            float bd11 = (gj + 1 <= r1) ? cB : ((gj + 1 == r1 + 1) ? 0.f : cB1);
            s[nt][0] = (s[nt][0] + bd00) * kScale;
            s[nt][1] = (s[nt][1] + bd01) * kScale;
            s[nt][2] = (s[nt][2] + bd10) * kScale;
            s[nt][3] = (s[nt][3] + bd11) * kScale;
            rmax0 = fmaxf(rmax0, fmaxf(s[nt][0], s[nt][1]));
            rmax1 = fmaxf(rmax1, fmaxf(s[nt][2], s[nt][3]));
        }
        rmax0 = fmaxf(rmax0, __shfl_xor_sync(~0u, rmax0, 1));
        rmax0 = fmaxf(rmax0, __shfl_xor_sync(~0u, rmax0, 2));
        rmax1 = fmaxf(rmax1, __shfl_xor_sync(~0u, rmax1, 1));
        rmax1 = fmaxf(rmax1, __shfl_xor_sync(~0u, rmax1, 2));
        float mn0 = fmaxf(m0v, rmax0), mn1 = fmaxf(m1v, rmax1);
        float al0 = __expf(m0v - mn0), al1 = __expf(m1v - mn1);
        float rs0 = 0.f, rs1 = 0.f;
        #pragma unroll
        for (int nt = 0; nt < 8; nt++) {
            float p0 = __expf(s[nt][0] - mn0), p1 = __expf(s[nt][1] - mn0);
            float p2 = __expf(s[nt][2] - mn1), p3 = __expf(s[nt][3] - mn1);
            rs0 += p0 + p1; rs1 += p2 + p3;
            *(__half2*)&Ps[w * 16 + gid][nt * 8 + tig * 2]     = __floats2half2_rn(p0, p1);
            *(__half2*)&Ps[w * 16 + gid + 8][nt * 8 + tig * 2] = __floats2half2_rn(p2, p3);
        }
        rs0 += __shfl_xor_sync(~0u, rs0, 1);
        rs0 += __shfl_xor_sync(~0u, rs0, 2);
        rs1 += __shfl_xor_sync(~0u, rs1, 1);
        rs1 += __shfl_xor_sync(~0u, rs1, 2);
        l0 = l0 * al0 + rs0; l1 = l1 * al1 + rs1;
        m0v = mn0; m1v = mn1;
        #pragma unroll
        for (int nt = 0; nt < 8; nt++) {
            o[nt][0] *= al0; o[nt][1] *= al0;
            o[nt][2] *= al1; o[nt][3] *= al1;
        }
        __syncwarp();

        // O += P V   (B frags from Vt[d][j])
        #pragma unroll
        for (int kb = 0; kb < 64; kb += 16) {
            unsigned a[4];
            a[0] = *(unsigned*)&Ps[w * 16 + gid][kb + tig * 2];
            a[1] = *(unsigned*)&Ps[w * 16 + gid + 8][kb + tig * 2];
            a[2] = *(unsigned*)&Ps[w * 16 + gid][kb + 8 + tig * 2];
            a[3] = *(unsigned*)&Ps[w * 16 + gid + 8][kb + 8 + tig * 2];
            #pragma unroll
            for (int nt = 0; nt < 8; nt++) {
                unsigned bf[2];
                bf[0] = *(unsigned*)&Vt[nt * 8 + gid][kb + tig * 2];
                bf[1] = *(unsigned*)&Vt[nt * 8 + gid][kb + 8 + tig * 2];
                mma16816(o[nt], a, bf);
            }
        }
    }

    float inv0 = 1.f / l0, inv1 = 1.f / l1;
    #pragma unroll
    for (int nt = 0; nt < 8; nt++) {
        int d = nt * 8 + tig * 2;
        *(__half2*)&g_av[((size_t)r0 * kB + b) * kD + h * kDh + d] =
            __floats2half2_rn(o[nt][0] * inv0, o[nt][1] * inv0);
        *(__half2*)&g_av[((size_t)r1 * kB + b) * kD + h * kDh + d] =
            __floats2half2_rn(o[nt][2] * inv1, o[nt][3] * inv1);
    }
}

// ---------------------- Output GEMM + residual (fp16 mma) --------------------
__global__ __launch_bounds__(256) void gemm_out_kernel(float* __restrict__ out) {
    __shared__ __half As[128][40];
    __shared__ __half Bs[128][40];
    int tid = threadIdx.x, lane = tid & 31, w = tid >> 5;
    int gid = lane >> 2, tig = lane & 3;
    int m0 = blockIdx.y * 128, n0 = blockIdx.x * 128;
    int wm = w >> 2, wn = w & 3;
    float acc[4][4][4] = {};
    for (int k0 = 0; k0 < kD; k0 += 32) {
        #pragma unroll
        for (int t = 0; t < 2; t++) {
            int idx = tid + t * 256;
            int r = idx >> 2, c = (idx & 3) * 8;
            *(float4*)&As[r][c] = *(const float4*)&g_av[(size_t)(m0 + r) * kD + k0 + c];
            *(float4*)&Bs[r][c] = *(const float4*)&g_wo_t[(size_t)(n0 + r) * kD + k0 + c];
        }
        __syncthreads();
        #pragma unroll
        for (int kb = 0; kb < 32; kb += 16) {
            unsigned a[4][4], b[4][2];
            #pragma unroll
            for (int mi = 0; mi < 4; mi++) {
                int r = wm * 64 + mi * 16 + gid;
                a[mi][0] = *(unsigned*)&As[r][kb + tig * 2];
                a[mi][1] = *(unsigned*)&As[r + 8][kb + tig * 2];
                a[mi][2] = *(unsigned*)&As[r][kb + 8 + tig * 2];
                a[mi][3] = *(unsigned*)&As[r + 8][kb + 8 + tig * 2];
            }
            #pragma unroll
            for (int ni = 0; ni < 4; ni++) {
                int n = wn * 32 + ni * 8 + gid;
                b[ni][0] = *(unsigned*)&Bs[n][kb + tig * 2];
                b[ni][1] = *(unsigned*)&Bs[n][kb + 8 + tig * 2];
            }
            #pragma unroll
            for (int mi = 0; mi < 4; mi++)
                #pragma unroll
                for (int ni = 0; ni < 4; ni++)
                    mma16816(acc[mi][ni], a[mi], b[ni]);
        }
        __syncthreads();
    }
    #pragma unroll
    for (int mi = 0; mi < 4; mi++) {
        int r0e = m0 + wm * 64 + mi * 16 + gid, r1e = r0e + 8;
        #pragma unroll
        for (int ni = 0; ni < 4; ni++) {
            int c0 = n0 + wn * 32 + ni * 8 + tig * 2;
            float2 x0 = *(const float2*)&g_xn[(size_t)r0e * kD + c0];
            float2 x1 = *(const float2*)&g_xn[(size_t)r1e * kD + c0];
            float2 o0 = { acc[mi][ni][0] + x0.x, acc[mi][ni][1] + x0.y };
            float2 o1 = { acc[mi][ni][2] + x1.x, acc[mi][ni][3] + x1.y };
            *(float2*)&out[(size_t)r0e * kD + c0] = o0;
            *(float2*)&out[(size_t)r1e * kD + c0] = o1;
        }
    }
}

// --------------------------------- launch ------------------------------------
extern "C" void kernel_launch(void* const* d_in, const int* in_sizes, int n_in,
                              void* d_out, int out_size) {
    const float* x    = (const float*)d_in[0];
    const float* r    = (const float*)d_in[1];
    const float* rw   = (const float*)d_in[2];
    const float* rr   = (const float*)d_in[3];
    const float* ln_g = (const float*)d_in[4];
    const float* ln_b = (const float*)d_in[5];
    const float* Wqkv = (const float*)d_in[6];
    const float* Wr   = (const float*)d_in[7];
    const float* Wo   = (const float*)d_in[8];
    float* out = (float*)d_out;

    ln_kernel<<<kRows, 256>>>(x, ln_g, ln_b);
    convw_kernel<0><<<dim3(3 * kD / 32, kD / 32), dim3(32, 8)>>>(Wqkv);
    convw_kernel<1><<<dim3(kD / 32, kD / 32), dim3(32, 8)>>>(Wo);
    rk0_kernel<<<4, 256>>>(r, Wr);
    gemm_qkv_kernel<<<dim3(3 * kD / 128, kRows / 128), 256>>>(rw);
    cbd_kernel<<<kS * kB * kH / 8, 256>>>(rw, rr);
    flash_kernel<<<dim3(kS / 64, kH, kB), 128>>>();
    gemm_out_kernel<<<dim3(kD / 128, kRows / 128), 256>>>(out);
}

// round 8
// speedup vs baseline: 5.2726x; 1.1815x over previous
#include <cuda_runtime.h>
#include <cuda_fp16.h>
#include <math.h>

namespace {
constexpr int kS = 2048, kB = 2, kD = 1024, kH = 16, kDh = 64;
constexpr int kRows = kS * kB;            // 4096
constexpr float kScale = 0.125f;          // 1/sqrt(64)
constexpr float kEps = 1e-5f;
constexpr int kRkChunks = 16;             // k-split for rk0
}

// ------------------------- scratch (static device memory) -------------------
// NOTE: these symbols are ONLY referenced inside device code — never passed
// as kernel arguments from host (host-side symbol decay gives the host shadow
// address, which ATS dereferences into the wrong memory silently).
__device__ float  g_xn[kRows * kD];                // normed input fp32 (residual)
__device__ __half g_xn_h[kRows * kD];              // normed input fp16 (GEMM A)
__device__ __half g_wqkv_t[3 * kD * kD];           // Wqkv^T  [n=3072][k=1024]
__device__ __half g_wo_t[kD * kD];                 // Wo^T    [n=1024][k=1024]
__device__ __half g_q[kB * kH * kS * kDh];         // q + rw  [b][h][s][d]
__device__ __half g_k[kB * kH * kS * kDh];         // [b][h][s][d]
__device__ __half g_vt[kB * kH * kDh * kS];        // V^T [b][h][d][s]
__device__ __half g_av[kRows * kD];                // attn out fp16 [row][h*64+d]
__device__ float  g_rk0p[kRkChunks * kD];          // rk0 partial sums
__device__ float  g_rk0[kD];                       // r @ Wr
__device__ float  g_c[kS * kB * kH];               // BD constants c[i,b,h]

// ------------------------------ mma helper -----------------------------------
__device__ __forceinline__ void mma16816(float* c, const unsigned* a, const unsigned* b) {
    asm volatile(
        "mma.sync.aligned.m16n8k16.row.col.f32.f16.f16.f32 "
        "{%0,%1,%2,%3},{%4,%5,%6,%7},{%8,%9},{%0,%1,%2,%3};\n"
        : "+f"(c[0]), "+f"(c[1]), "+f"(c[2]), "+f"(c[3])
        : "r"(a[0]), "r"(a[1]), "r"(a[2]), "r"(a[3]), "r"(b[0]), "r"(b[1]));
}

// ------------------------------ LayerNorm -----------------------------------
__global__ void ln_kernel(const float* __restrict__ x,
                          const float* __restrict__ gamma,
                          const float* __restrict__ beta) {
    int row = blockIdx.x;
    int t = threadIdx.x;
    const float4 v = reinterpret_cast<const float4*>(x + (size_t)row * kD)[t];
    float s1 = v.x + v.y + v.z + v.w;
    float s2 = v.x*v.x + v.y*v.y + v.z*v.z + v.w*v.w;
    #pragma unroll
    for (int o = 16; o; o >>= 1) {
        s1 += __shfl_xor_sync(~0u, s1, o);
        s2 += __shfl_xor_sync(~0u, s2, o);
    }
    __shared__ float sm1[8], sm2[8];
    int w = t >> 5, lane = t & 31;
    if (lane == 0) { sm1[w] = s1; sm2[w] = s2; }
    __syncthreads();
    if (w == 0) {
        s1 = (lane < 8) ? sm1[lane] : 0.f;
        s2 = (lane < 8) ? sm2[lane] : 0.f;
        #pragma unroll
        for (int o = 4; o; o >>= 1) {
            s1 += __shfl_xor_sync(~0u, s1, o);
            s2 += __shfl_xor_sync(~0u, s2, o);
        }
        if (lane == 0) { sm1[0] = s1; sm2[0] = s2; }
    }
    __syncthreads();
    float mu = sm1[0] * (1.f / kD);
    float var = sm2[0] * (1.f / kD) - mu * mu;
    float rstd = rsqrtf(var + kEps);
    const float4 gv = reinterpret_cast<const float4*>(gamma)[t];
    const float4 bv = reinterpret_cast<const float4*>(beta)[t];
    float4 o;
    o.x = (v.x - mu) * rstd * gv.x + bv.x;
    o.y = (v.y - mu) * rstd * gv.y + bv.y;
    o.z = (v.z - mu) * rstd * gv.z + bv.z;
    o.w = (v.w - mu) * rstd * gv.w + bv.w;
    reinterpret_cast<float4*>(g_xn + (size_t)row * kD)[t] = o;
    *reinterpret_cast<__half2*>(&g_xn_h[(size_t)row * kD + t * 4])     = __floats2half2_rn(o.x, o.y);
    *reinterpret_cast<__half2*>(&g_xn_h[(size_t)row * kD + t * 4 + 2]) = __floats2half2_rn(o.z, o.w);
}

// --------------- weight transpose + fp32 -> fp16 conversion ------------------
// WHICH=0: g_wqkv_t[n][k] = Wqkv[k][n] (N=3072); WHICH=1: g_wo_t = Wo^T (N=1024)
template <int WHICH>
__global__ void convw_kernel(const float* __restrict__ src) {
    constexpr int K = kD;
    constexpr int N = (WHICH == 0) ? 3 * kD : kD;
    __half* dst = (WHICH == 0) ? g_wqkv_t : g_wo_t;   // resolved in device code
    __shared__ float tile[32][33];
    int n0 = blockIdx.x * 32, k0 = blockIdx.y * 32;
    int tx = threadIdx.x, ty = threadIdx.y;
    #pragma unroll
    for (int i = 0; i < 32; i += 8)
        tile[ty + i][tx] = src[(size_t)(k0 + ty + i) * N + n0 + tx];
    __syncthreads();
    #pragma unroll
    for (int i = 0; i < 32; i += 8)
        dst[(size_t)(n0 + ty + i) * K + k0 + tx] = __float2half(tile[tx][ty + i]);
}

// ----------------------------- rk0 = r @ Wr (k-split) ------------------------
__global__ void rk0_part_kernel(const float* __restrict__ r, const float* __restrict__ Wr) {
    int col = blockIdx.x * 256 + threadIdx.x;          // 0..1023
    int chunk = blockIdx.y;                            // 0..15
    int d0 = chunk * (kD / kRkChunks);
    float s = 0.f;
    #pragma unroll
    for (int i = 0; i < kD / kRkChunks; i++)
        s += r[d0 + i] * Wr[(size_t)(d0 + i) * kD + col];
    g_rk0p[chunk * kD + col] = s;
}
__global__ void rk0_reduce_kernel() {
    int col = blockIdx.x * 256 + threadIdx.x;
    float s = 0.f;
    #pragma unroll
    for (int c = 0; c < kRkChunks; c++) s += g_rk0p[c * kD + col];
    g_rk0[col] = s;
}

// ------------------------------ QKV GEMM (fp16 mma) --------------------------
// C[4096,3072] = xn_h @ Wqkv ; scatter fp16 into g_q(+rw)/g_k/g_vt
__global__ __launch_bounds__(256) void gemm_qkv_kernel(const float* __restrict__ rw) {
    __shared__ __half As[128][40];
    __shared__ __half Bs[128][40];
    int tid = threadIdx.x, lane = tid & 31, w = tid >> 5;
    int gid = lane >> 2, tig = lane & 3;
    int m0 = blockIdx.y * 128, n0 = blockIdx.x * 128;
    int wm = w >> 2, wn = w & 3;
    float acc[4][4][4] = {};
    for (int k0 = 0; k0 < kD; k0 += 32) {
        #pragma unroll
        for (int t = 0; t < 2; t++) {
            int idx = tid + t * 256;
            int r = idx >> 2, c = (idx & 3) * 8;
            *(float4*)&As[r][c] = *(const float4*)&g_xn_h[(size_t)(m0 + r) * kD + k0 + c];
            *(float4*)&Bs[r][c] = *(const float4*)&g_wqkv_t[(size_t)(n0 + r) * kD + k0 + c];
        }
        __syncthreads();
        #pragma unroll
        for (int kb = 0; kb < 32; kb += 16) {
            unsigned a[4][4], b[4][2];
            #pragma unroll
            for (int mi = 0; mi < 4; mi++) {
                int r = wm * 64 + mi * 16 + gid;
                a[mi][0] = *(unsigned*)&As[r][kb + tig * 2];
                a[mi][1] = *(unsigned*)&As[r + 8][kb + tig * 2];
                a[mi][2] = *(unsigned*)&As[r][kb + 8 + tig * 2];
                a[mi][3] = *(unsigned*)&As[r + 8][kb + 8 + tig * 2];
            }
            #pragma unroll
            for (int ni = 0; ni < 4; ni++) {
                int n = wn * 32 + ni * 8 + gid;
                b[ni][0] = *(unsigned*)&Bs[n][kb + tig * 2];
                b[ni][1] = *(unsigned*)&Bs[n][kb + 8 + tig * 2];
            }
            #pragma unroll
            for (int mi = 0; mi < 4; mi++)
                #pragma unroll
                for (int ni = 0; ni < 4; ni++)
                    mma16816(acc[mi][ni], a[mi], b[ni]);
        }
        __syncthreads();
    }
    // epilogue: scatter to q/k/vt
    #pragma unroll
    for (int mi = 0; mi < 4; mi++) {
        int r0e = m0 + wm * 64 + mi * 16 + gid, r1e = r0e + 8;
        int s0 = r0e >> 1, b0e = r0e & 1;
        int s1 = r1e >> 1, b1e = r1e & 1;
        #pragma unroll
        for (int ni = 0; ni < 4; ni++) {
            int c0 = n0 + wn * 32 + ni * 8 + tig * 2;
            int part = c0 >> 10, rem = c0 & 1023, hh = rem >> 6, d = rem & 63;
            float v00 = acc[mi][ni][0], v01 = acc[mi][ni][1];
            float v10 = acc[mi][ni][2], v11 = acc[mi][ni][3];
            if (part == 0) {
                float w0 = rw[rem], w1 = rw[rem + 1];
                *(__half2*)&g_q[(((size_t)(b0e * kH + hh)) * kS + s0) * kDh + d] =
                    __floats2half2_rn(v00 + w0, v01 + w1);
                *(__half2*)&g_q[(((size_t)(b1e * kH + hh)) * kS + s1) * kDh + d] =
                    __floats2half2_rn(v10 + w0, v11 + w1);
            } else if (part == 1) {
                *(__half2*)&g_k[(((size_t)(b0e * kH + hh)) * kS + s0) * kDh + d] =
                    __floats2half2_rn(v00, v01);
                *(__half2*)&g_k[(((size_t)(b1e * kH + hh)) * kS + s1) * kDh + d] =
                    __floats2half2_rn(v10, v11);
            } else {
                size_t vb0 = (size_t)(b0e * kH + hh) * kDh;
                size_t vb1 = (size_t)(b1e * kH + hh) * kDh;
                g_vt[(vb0 + d) * kS + s0]     = __float2half(v00);
                g_vt[(vb0 + d + 1) * kS + s0] = __float2half(v01);
                g_vt[(vb1 + d) * kS + s1]     = __float2half(v10);
                g_vt[(vb1 + d + 1) * kS + s1] = __float2half(v11);
            }
        }
    }
}

// ----------------- BD constants: c[i,b,h] = (q + rr)·rk0 ---------------------
__global__ void cbd_kernel(const float* __restrict__ rw, const float* __restrict__ rr) {
    int warp = blockIdx.x * 8 + (threadIdx.x >> 5);
    int lane = threadIdx.x & 31;
    int h = warp & 15, bb = (warp >> 4) & 1, i = warp >> 5;
    float s = 0.f;
    #pragma unroll
    for (int t = 0; t < 2; t++) {
        int d = lane + t * 32;
        size_t qi = (((size_t)(bb * kH + h)) * kS + i) * kDh + d;
        int hd = h * kDh + d;
        s += (__half2float(g_q[qi]) - rw[hd] + rr[hd]) * g_rk0[hd];
    }
    #pragma unroll
    for (int o = 16; o; o >>= 1) s += __shfl_xor_sync(~0u, s, o);
    if (lane == 0) g_c[((size_t)i * kB + bb) * kH + h] = s;
}

// ------------------------- Flash attention (fp16 mma) ------------------------
// Block: 128 thr = 4 warps, one (b,h), 64 query rows (16 per warp), key tiles 64.
__global__ __launch_bounds__(128) void flash_kernel() {
    __shared__ __half Qs[64][72];
    __shared__ __half Ks[64][72];
    __shared__ __half Vt[64][72];    // [d][j]
    __shared__ __half Ps[64][72];
    int b = blockIdx.z, h = blockIdx.y, i0 = blockIdx.x * 64;
    int tid = threadIdx.x, w = tid >> 5, lane = tid & 31;
    int gid = lane >> 2, tig = lane & 3;
    size_t kbase = ((size_t)(b * kH + h)) * kS * kDh;
    size_t vbase = ((size_t)(b * kH + h)) * kDh * kS;

    #pragma unroll
    for (int t = 0; t < 4; t++) {
        int idx = tid + t * 128;
        int r = idx >> 3, c = (idx & 7) * 8;
        *(float4*)&Qs[r][c] = *(const float4*)&g_q[kbase + (size_t)(i0 + r) * kDh + c];
    }

    int r0 = i0 + w * 16 + gid, r1 = r0 + 8;
    float cA  = g_c[((size_t)r0 * kB + b) * kH + h];
    float cA1 = (r0 + 1 < kS) ? g_c[((size_t)(r0 + 1) * kB + b) * kH + h] : 0.f;
    float cB  = g_c[((size_t)r1 * kB + b) * kH + h];
    float cB1 = (r1 + 1 < kS) ? g_c[((size_t)(r1 + 1) * kB + b) * kH + h] : 0.f;

    float m0v = -1e30f, m1v = -1e30f, l0 = 0.f, l1 = 0.f;
    float o[8][4] = {};

    for (int j0 = 0; j0 < kS; j0 += 64) {
        __syncthreads();
        #pragma unroll
        for (int t = 0; t < 4; t++) {
            int idx = tid + t * 128;
            int r = idx >> 3, c = (idx & 7) * 8;
            *(float4*)&Ks[r][c] = *(const float4*)&g_k[kbase + (size_t)(j0 + r) * kDh + c];
            *(float4*)&Vt[r][c] = *(const float4*)&g_vt[vbase + (size_t)r * kS + j0 + c];
        }
        __syncthreads();

        // S = Q K^T
        float s[8][4] = {};
        #pragma unroll
        for (int kb = 0; kb < 64; kb += 16) {
            unsigned a[4];
            a[0] = *(unsigned*)&Qs[w * 16 + gid][kb + tig * 2];
            a[1] = *(unsigned*)&Qs[w * 16 + gid + 8][kb + tig * 2];
            a[2] = *(unsigned*)&Qs[w * 16 + gid][kb + 8 + tig * 2];
            a[3] = *(unsigned*)&Qs[w * 16 + gid + 8][kb + 8 + tig * 2];
            #pragma unroll
            for (int nt = 0; nt < 8; nt++) {
                unsigned bf[2];
                bf[0] = *(unsigned*)&Ks[nt * 8 + gid][kb + tig * 2];
                bf[1] = *(unsigned*)&Ks[nt * 8 + gid][kb + 8 + tig * 2];
                mma16816(s[nt], a, bf);
            }
        }

        // BD + scale + online softmax (fp32)
        float rmax0 = -1e30f, rmax1 = -1e30f;
        #pragma unroll
        for (int nt = 0; nt < 8; nt++) {
            int gj = j0 + nt * 8 + tig * 2;
            float bd00 = (gj <= r0) ? cA : ((gj == r0 + 1) ? 0.f : cA1);
            float bd01 = (gj + 1 <= r0) ? cA : ((gj + 1 == r0 + 1) ? 0.f : cA1);
            float bd10 = (gj <= r1) ? cB : ((gj == r1 + 1) ? 0.f : cB1);
            float bd11 = (gj + 1 <= r1) ? cB : ((gj + 1 == r1 + 1) ? 0.f : cB1);
            s[nt][0] = (s[nt][0] + bd00) * kScale;
            s[nt][1] = (s[nt][1] + bd01) * kScale;
            s[nt][2] = (s[nt][2] + bd10) * kScale;
            s[nt][3] = (s[nt][3] + bd11) * kScale;
            rmax0 = fmaxf(rmax0, fmaxf(s[nt][0], s[nt][1]));
            rmax1 = fmaxf(rmax1, fmaxf(s[nt][2], s[nt][3]));
        }
        rmax0 = fmaxf(rmax0, __shfl_xor_sync(~0u, rmax0, 1));
        rmax0 = fmaxf(rmax0, __shfl_xor_sync(~0u, rmax0, 2));
        rmax1 = fmaxf(rmax1, __shfl_xor_sync(~0u, rmax1, 1));
        rmax1 = fmaxf(rmax1, __shfl_xor_sync(~0u, rmax1, 2));
        float mn0 = fmaxf(m0v, rmax0), mn1 = fmaxf(m1v, rmax1);
        float al0 = __expf(m0v - mn0), al1 = __expf(m1v - mn1);
        float rs0 = 0.f, rs1 = 0.f;
        #pragma unroll
        for (int nt = 0; nt < 8; nt++) {
            float p0 = __expf(s[nt][0] - mn0), p1 = __expf(s[nt][1] - mn0);
            float p2 = __expf(s[nt][2] - mn1), p3 = __expf(s[nt][3] - mn1);
            rs0 += p0 + p1; rs1 += p2 + p3;
            *(__half2*)&Ps[w * 16 + gid][nt * 8 + tig * 2]     = __floats2half2_rn(p0, p1);
            *(__half2*)&Ps[w * 16 + gid + 8][nt * 8 + tig * 2] = __floats2half2_rn(p2, p3);
        }
        rs0 += __shfl_xor_sync(~0u, rs0, 1);
        rs0 += __shfl_xor_sync(~0u, rs0, 2);
        rs1 += __shfl_xor_sync(~0u, rs1, 1);
        rs1 += __shfl_xor_sync(~0u, rs1, 2);
        l0 = l0 * al0 + rs0; l1 = l1 * al1 + rs1;
        m0v = mn0; m1v = mn1;
        #pragma unroll
        for (int nt = 0; nt < 8; nt++) {
            o[nt][0] *= al0; o[nt][1] *= al0;
            o[nt][2] *= al1; o[nt][3] *= al1;
        }
        __syncwarp();

        // O += P V   (B frags from Vt[d][j])
        #pragma unroll
        for (int kb = 0; kb < 64; kb += 16) {
            unsigned a[4];
            a[0] = *(unsigned*)&Ps[w * 16 + gid][kb + tig * 2];
            a[1] = *(unsigned*)&Ps[w * 16 + gid + 8][kb + tig * 2];
            a[2] = *(unsigned*)&Ps[w * 16 + gid][kb + 8 + tig * 2];
            a[3] = *(unsigned*)&Ps[w * 16 + gid + 8][kb + 8 + tig * 2];
            #pragma unroll
            for (int nt = 0; nt < 8; nt++) {
                unsigned bf[2];
                bf[0] = *(unsigned*)&Vt[nt * 8 + gid][kb + tig * 2];
                bf[1] = *(unsigned*)&Vt[nt * 8 + gid][kb + 8 + tig * 2];
                mma16816(o[nt], a, bf);
            }
        }
    }

    float inv0 = 1.f / l0, inv1 = 1.f / l1;
    #pragma unroll
    for (int nt = 0; nt < 8; nt++) {
        int d = nt * 8 + tig * 2;
        *(__half2*)&g_av[((size_t)r0 * kB + b) * kD + h * kDh + d] =
            __floats2half2_rn(o[nt][0] * inv0, o[nt][1] * inv0);
        *(__half2*)&g_av[((size_t)r1 * kB + b) * kD + h * kDh + d] =
            __floats2half2_rn(o[nt][2] * inv1, o[nt][3] * inv1);
    }
}

// ---------------------- Output GEMM + residual (fp16 mma) --------------------
__global__ __launch_bounds__(256) void gemm_out_kernel(float* __restrict__ out) {
    __shared__ __half As[128][40];
    __shared__ __half Bs[128][40];
    int tid = threadIdx.x, lane = tid & 31, w = tid >> 5;
    int gid = lane >> 2, tig = lane & 3;
    int m0 = blockIdx.y * 128, n0 = blockIdx.x * 128;
    int wm = w >> 2, wn = w & 3;
    float acc[4][4][4] = {};
    for (int k0 = 0; k0 < kD; k0 += 32) {
        #pragma unroll
        for (int t = 0; t < 2; t++) {
            int idx = tid + t * 256;
            int r = idx >> 2, c = (idx & 3) * 8;
            *(float4*)&As[r][c] = *(const float4*)&g_av[(size_t)(m0 + r) * kD + k0 + c];
            *(float4*)&Bs[r][c] = *(const float4*)&g_wo_t[(size_t)(n0 + r) * kD + k0 + c];
        }
        __syncthreads();
        #pragma unroll
        for (int kb = 0; kb < 32; kb += 16) {
            unsigned a[4][4], b[4][2];
            #pragma unroll
            for (int mi = 0; mi < 4; mi++) {
                int r = wm * 64 + mi * 16 + gid;
                a[mi][0] = *(unsigned*)&As[r][kb + tig * 2];
                a[mi][1] = *(unsigned*)&As[r + 8][kb + tig * 2];
                a[mi][2] = *(unsigned*)&As[r][kb + 8 + tig * 2];
                a[mi][3] = *(unsigned*)&As[r + 8][kb + 8 + tig * 2];
            }
            #pragma unroll
            for (int ni = 0; ni < 4; ni++) {
                int n = wn * 32 + ni * 8 + gid;
                b[ni][0] = *(unsigned*)&Bs[n][kb + tig * 2];
                b[ni][1] = *(unsigned*)&Bs[n][kb + 8 + tig * 2];
            }
            #pragma unroll
            for (int mi = 0; mi < 4; mi++)
                #pragma unroll
                for (int ni = 0; ni < 4; ni++)
                    mma16816(acc[mi][ni], a[mi], b[ni]);
        }
        __syncthreads();
    }
    #pragma unroll
    for (int mi = 0; mi < 4; mi++) {
        int r0e = m0 + wm * 64 + mi * 16 + gid, r1e = r0e + 8;
        #pragma unroll
        for (int ni = 0; ni < 4; ni++) {
            int c0 = n0 + wn * 32 + ni * 8 + tig * 2;
            float2 x0 = *(const float2*)&g_xn[(size_t)r0e * kD + c0];
            float2 x1 = *(const float2*)&g_xn[(size_t)r1e * kD + c0];
            float2 o0 = { acc[mi][ni][0] + x0.x, acc[mi][ni][1] + x0.y };
            float2 o1 = { acc[mi][ni][2] + x1.x, acc[mi][ni][3] + x1.y };
            *(float2*)&out[(size_t)r0e * kD + c0] = o0;
            *(float2*)&out[(size_t)r1e * kD + c0] = o1;
        }
    }
}

// --------------------------------- launch ------------------------------------
extern "C" void kernel_launch(void* const* d_in, const int* in_sizes, int n_in,
                              void* d_out, int out_size) {
    const float* x    = (const float*)d_in[0];
    const float* r    = (const float*)d_in[1];
    const float* rw   = (const float*)d_in[2];
    const float* rr   = (const float*)d_in[3];
    const float* ln_g = (const float*)d_in[4];
    const float* ln_b = (const float*)d_in[5];
    const float* Wqkv = (const float*)d_in[6];
    const float* Wr   = (const float*)d_in[7];
    const float* Wo   = (const float*)d_in[8];
    float* out = (float*)d_out;

    ln_kernel<<<kRows, 256>>>(x, ln_g, ln_b);
    convw_kernel<0><<<dim3(3 * kD / 32, kD / 32), dim3(32, 8)>>>(Wqkv);
    convw_kernel<1><<<dim3(kD / 32, kD / 32), dim3(32, 8)>>>(Wo);
    rk0_part_kernel<<<dim3(kD / 256, kRkChunks), 256>>>(r, Wr);
    rk0_reduce_kernel<<<kD / 256, 256>>>();
    gemm_qkv_kernel<<<dim3(3 * kD / 128, kRows / 128), 256>>>(rw);
    cbd_kernel<<<kS * kB * kH / 8, 256>>>(rw, rr);
    flash_kernel<<<dim3(kS / 64, kH, kB), 128>>>();
    gemm_out_kernel<<<dim3(kD / 128, kRows / 128), 256>>>(out);
}

// round 9
// speedup vs baseline: 5.7834x; 1.0969x over previous
#include <cuda_runtime.h>
#include <cuda_fp16.h>
#include <math.h>

namespace {
constexpr int kS = 2048, kB = 2, kD = 1024, kH = 16, kDh = 64;
constexpr int kRows = kS * kB;            // 4096
constexpr float kScale = 0.125f;          // 1/sqrt(64)
constexpr float kEps = 1e-5f;
constexpr int kRkChunks = 16;             // k-split for rk0
}

// ------------------------- scratch (static device memory) -------------------
// NOTE: only referenced inside device code — never passed as kernel args.
__device__ float  g_xn[kRows * kD];
__device__ __half g_xn_h[kRows * kD];
__device__ __half g_wqkv_t[3 * kD * kD];           // Wqkv^T [n][k]
__device__ __half g_wo_t[kD * kD];                 // Wo^T [n][k]
__device__ __half g_q[kB * kH * kS * kDh];         // q + rw [b][h][s][d]
__device__ __half g_k[kB * kH * kS * kDh];
__device__ __half g_vt[kB * kH * kDh * kS];        // V^T [b][h][d][s]
__device__ __half g_av[kRows * kD];
__device__ float  g_rk0p[kRkChunks * kD];
__device__ float  g_rk0[kD];
__device__ float  g_c[kS * kB * kH];

// ------------------------------ asm helpers ----------------------------------
__device__ __forceinline__ void mma16816(float* c, const unsigned* a, const unsigned* b) {
    asm volatile(
        "mma.sync.aligned.m16n8k16.row.col.f32.f16.f16.f32 "
        "{%0,%1,%2,%3},{%4,%5,%6,%7},{%8,%9},{%0,%1,%2,%3};\n"
        : "+f"(c[0]), "+f"(c[1]), "+f"(c[2]), "+f"(c[3])
        : "r"(a[0]), "r"(a[1]), "r"(a[2]), "r"(a[3]), "r"(b[0]), "r"(b[1]));
}
__device__ __forceinline__ void ldsm_x4(unsigned* r, unsigned addr) {
    asm volatile("ldmatrix.sync.aligned.m8n8.x4.shared.b16 {%0,%1,%2,%3}, [%4];\n"
                 : "=r"(r[0]), "=r"(r[1]), "=r"(r[2]), "=r"(r[3]) : "r"(addr));
}
__device__ __forceinline__ unsigned smem_u32(const void* p) {
    return (unsigned)__cvta_generic_to_shared(p);
}
__device__ __forceinline__ void cp_async16(unsigned dst, const void* src) {
    asm volatile("cp.async.ca.shared.global [%0], [%1], 16;\n"
                 :: "r"(dst), "l"(__cvta_generic_to_global(src)));
}
#define CP_COMMIT() asm volatile("cp.async.commit_group;\n")
#define CP_WAIT(n)  asm volatile("cp.async.wait_group %0;\n" :: "n"(n))

// ------------------------------ LayerNorm -----------------------------------
__global__ void ln_kernel(const float* __restrict__ x,
                          const float* __restrict__ gamma,
                          const float* __restrict__ beta) {
    int row = blockIdx.x;
    int t = threadIdx.x;
    const float4 v = reinterpret_cast<const float4*>(x + (size_t)row * kD)[t];
    float s1 = v.x + v.y + v.z + v.w;
    float s2 = v.x*v.x + v.y*v.y + v.z*v.z + v.w*v.w;
    #pragma unroll
    for (int o = 16; o; o >>= 1) {
        s1 += __shfl_xor_sync(~0u, s1, o);
        s2 += __shfl_xor_sync(~0u, s2, o);
    }
    __shared__ float sm1[8], sm2[8];
    int w = t >> 5, lane = t & 31;
    if (lane == 0) { sm1[w] = s1; sm2[w] = s2; }
    __syncthreads();
    if (w == 0) {
        s1 = (lane < 8) ? sm1[lane] : 0.f;
        s2 = (lane < 8) ? sm2[lane] : 0.f;
        #pragma unroll
        for (int o = 4; o; o >>= 1) {
            s1 += __shfl_xor_sync(~0u, s1, o);
            s2 += __shfl_xor_sync(~0u, s2, o);
        }
        if (lane == 0) { sm1[0] = s1; sm2[0] = s2; }
    }
    __syncthreads();
    float mu = sm1[0] * (1.f / kD);
    float var = sm2[0] * (1.f / kD) - mu * mu;
    float rstd = rsqrtf(var + kEps);
    const float4 gv = reinterpret_cast<const float4*>(gamma)[t];
    const float4 bv = reinterpret_cast<const float4*>(beta)[t];
    float4 o;
    o.x = (v.x - mu) * rstd * gv.x + bv.x;
    o.y = (v.y - mu) * rstd * gv.y + bv.y;
    o.z = (v.z - mu) * rstd * gv.z + bv.z;
    o.w = (v.w - mu) * rstd * gv.w + bv.w;
    reinterpret_cast<float4*>(g_xn + (size_t)row * kD)[t] = o;
    *reinterpret_cast<__half2*>(&g_xn_h[(size_t)row * kD + t * 4])     = __floats2half2_rn(o.x, o.y);
    *reinterpret_cast<__half2*>(&g_xn_h[(size_t)row * kD + t * 4 + 2]) = __floats2half2_rn(o.z, o.w);
}

// --------------- weight transpose + fp32 -> fp16 conversion ------------------
template <int WHICH>
__global__ void convw_kernel(const float* __restrict__ src) {
    constexpr int K = kD;
    constexpr int N = (WHICH == 0) ? 3 * kD : kD;
    __half* dst = (WHICH == 0) ? g_wqkv_t : g_wo_t;
    __shared__ float tile[32][33];
    int n0 = blockIdx.x * 32, k0 = blockIdx.y * 32;
    int tx = threadIdx.x, ty = threadIdx.y;
    #pragma unroll
    for (int i = 0; i < 32; i += 8)
        tile[ty + i][tx] = src[(size_t)(k0 + ty + i) * N + n0 + tx];
    __syncthreads();
    #pragma unroll
    for (int i = 0; i < 32; i += 8)
        dst[(size_t)(n0 + ty + i) * K + k0 + tx] = __float2half(tile[tx][ty + i]);
}

// ----------------------------- rk0 = r @ Wr (k-split) ------------------------
__global__ void rk0_part_kernel(const float* __restrict__ r, const float* __restrict__ Wr) {
    int col = blockIdx.x * 256 + threadIdx.x;
    int chunk = blockIdx.y;
    int d0 = chunk * (kD / kRkChunks);
    float s = 0.f;
    #pragma unroll
    for (int i = 0; i < kD / kRkChunks; i++)
        s += r[d0 + i] * Wr[(size_t)(d0 + i) * kD + col];
    g_rk0p[chunk * kD + col] = s;
}
__global__ void rk0_reduce_kernel() {
    int col = blockIdx.x * 256 + threadIdx.x;
    float s = 0.f;
    #pragma unroll
    for (int c = 0; c < kRkChunks; c++) s += g_rk0p[c * kD + col];
    g_rk0[col] = s;
}

// ------------------------------ QKV GEMM (fp16 mma, cp.async + ldmatrix) -----
__global__ __launch_bounds__(256) void gemm_qkv_kernel(const float* __restrict__ rw) {
    __shared__ __half As[2][128][40];
    __shared__ __half Bs[2][128][40];
    int tid = threadIdx.x, lane = tid & 31, w = tid >> 5;
    int gid = lane >> 2, tig = lane & 3;
    int m0 = blockIdx.y * 128, n0 = blockIdx.x * 128;
    int wm = w >> 2, wn = w & 3;
    constexpr unsigned stageB = 128 * 40 * 2;
    // ldmatrix lane address bases (stage 0)
    unsigned a_base = smem_u32(&As[0][wm * 64 + (lane & 15)][(lane >> 4) * 8]);
    unsigned b_base = smem_u32(&Bs[0][wn * 32 + (lane & 7) + ((lane >> 4) << 3)][((lane >> 3) & 1) * 8]);
    int lr = tid >> 2, lc = (tid & 3) * 8;       // loader: row, col(half)
    int lr2 = lr + 64;
    float acc[4][4][4] = {};

    // prologue: stage 0
    cp_async16(smem_u32(&As[0][lr][lc]),  &g_xn_h[(size_t)(m0 + lr) * kD + lc]);
    cp_async16(smem_u32(&As[0][lr2][lc]), &g_xn_h[(size_t)(m0 + lr2) * kD + lc]);
    cp_async16(smem_u32(&Bs[0][lr][lc]),  &g_wqkv_t[(size_t)(n0 + lr) * kD + lc]);
    cp_async16(smem_u32(&Bs[0][lr2][lc]), &g_wqkv_t[(size_t)(n0 + lr2) * kD + lc]);
    CP_COMMIT();

    constexpr int NIT = kD / 32;
    for (int it = 0; it < NIT; it++) {
        if (it + 1 < NIT) {
            int st = (it + 1) & 1, k0 = (it + 1) * 32;
            cp_async16(smem_u32(&As[st][lr][lc]),  &g_xn_h[(size_t)(m0 + lr) * kD + k0 + lc]);
            cp_async16(smem_u32(&As[st][lr2][lc]), &g_xn_h[(size_t)(m0 + lr2) * kD + k0 + lc]);
            cp_async16(smem_u32(&Bs[st][lr][lc]),  &g_wqkv_t[(size_t)(n0 + lr) * kD + k0 + lc]);
            cp_async16(smem_u32(&Bs[st][lr2][lc]), &g_wqkv_t[(size_t)(n0 + lr2) * kD + k0 + lc]);
            CP_COMMIT();
            CP_WAIT(1);
        } else {
            CP_WAIT(0);
        }
        __syncthreads();
        unsigned soff = (it & 1) * stageB;
        #pragma unroll
        for (int kb = 0; kb < 32; kb += 16) {
            unsigned a[4][4], b[2][4];
            #pragma unroll
            for (int mi = 0; mi < 4; mi++)
                ldsm_x4(a[mi], a_base + soff + (mi * 16 * 40 + kb) * 2);
            #pragma unroll
            for (int p = 0; p < 2; p++)
                ldsm_x4(b[p], b_base + soff + (p * 16 * 40 + kb) * 2);
            #pragma unroll
            for (int mi = 0; mi < 4; mi++)
                #pragma unroll
                for (int p = 0; p < 2; p++) {
                    mma16816(acc[mi][2 * p],     a[mi], b[p]);
                    mma16816(acc[mi][2 * p + 1], a[mi], b[p] + 2);
                }
        }
        __syncthreads();
    }
    // epilogue: scatter to q/k/vt
    #pragma unroll
    for (int mi = 0; mi < 4; mi++) {
        int r0e = m0 + wm * 64 + mi * 16 + gid, r1e = r0e + 8;
        int s0 = r0e >> 1, b0e = r0e & 1;
        int s1 = r1e >> 1, b1e = r1e & 1;
        #pragma unroll
        for (int ni = 0; ni < 4; ni++) {
            int c0 = n0 + wn * 32 + ni * 8 + tig * 2;
            int part = c0 >> 10, rem = c0 & 1023, hh = rem >> 6, d = rem & 63;
            float v00 = acc[mi][ni][0], v01 = acc[mi][ni][1];
            float v10 = acc[mi][ni][2], v11 = acc[mi][ni][3];
            if (part == 0) {
                float w0 = rw[rem], w1 = rw[rem + 1];
                *(__half2*)&g_q[(((size_t)(b0e * kH + hh)) * kS + s0) * kDh + d] =
                    __floats2half2_rn(v00 + w0, v01 + w1);
                *(__half2*)&g_q[(((size_t)(b1e * kH + hh)) * kS + s1) * kDh + d] =
                    __floats2half2_rn(v10 + w0, v11 + w1);
            } else if (part == 1) {
                *(__half2*)&g_k[(((size_t)(b0e * kH + hh)) * kS + s0) * kDh + d] =
                    __floats2half2_rn(v00, v01);
                *(__half2*)&g_k[(((size_t)(b1e * kH + hh)) * kS + s1) * kDh + d] =
                    __floats2half2_rn(v10, v11);
            } else {
                size_t vb0 = (size_t)(b0e * kH + hh) * kDh;
                size_t vb1 = (size_t)(b1e * kH + hh) * kDh;
                g_vt[(vb0 + d) * kS + s0]     = __float2half(v00);
                g_vt[(vb0 + d + 1) * kS + s0] = __float2half(v01);
                g_vt[(vb1 + d) * kS + s1]     = __float2half(v10);
                g_vt[(vb1 + d + 1) * kS + s1] = __float2half(v11);
            }
        }
    }
}

// ----------------- BD constants: c[i,b,h] = (q + rr)·rk0 ---------------------
__global__ void cbd_kernel(const float* __restrict__ rw, const float* __restrict__ rr) {
    int warp = blockIdx.x * 8 + (threadIdx.x >> 5);
    int lane = threadIdx.x & 31;
    int h = warp & 15, bb = (warp >> 4) & 1, i = warp >> 5;
    float s = 0.f;
    #pragma unroll
    for (int t = 0; t < 2; t++) {
        int d = lane + t * 32;
        size_t qi = (((size_t)(bb * kH + h)) * kS + i) * kDh + d;
        int hd = h * kDh + d;
        s += (__half2float(g_q[qi]) - rw[hd] + rr[hd]) * g_rk0[hd];
    }
    #pragma unroll
    for (int o = 16; o; o >>= 1) s += __shfl_xor_sync(~0u, s, o);
    if (lane == 0) g_c[((size_t)i * kB + bb) * kH + h] = s;
}

// ------------------------- Flash attention (fp16 mma, 128q, reg-P) -----------
// Block: 256 thr = 8 warps, one (b,h), 128 query rows (16 per warp), key tiles 64.
__global__ __launch_bounds__(256) void flash_kernel() {
    __shared__ __half Qs[128][72];
    __shared__ __half Ks[64][72];
    __shared__ __half Vt[64][72];    // [d][j]
    int b = blockIdx.z, h = blockIdx.y, i0 = blockIdx.x * 128;
    int tid = threadIdx.x, w = tid >> 5, lane = tid & 31;
    int gid = lane >> 2, tig = lane & 3;
    size_t kbase = ((size_t)(b * kH + h)) * kS * kDh;
    size_t vbase = ((size_t)(b * kH + h)) * kDh * kS;

    // load Q (128 rows x 64 halfs)
    #pragma unroll
    for (int t = 0; t < 4; t++) {
        int idx = tid + t * 256;
        int r = idx >> 3, c = (idx & 7) * 8;
        *(float4*)&Qs[r][c] = *(const float4*)&g_q[kbase + (size_t)(i0 + r) * kDh + c];
    }

    // ldmatrix lane-address bases
    unsigned qa_base  = smem_u32(&Qs[w * 16 + (lane & 15)][(lane >> 4) * 8]);
    int brow = (lane & 7) + ((lane >> 4) << 3);
    int bcol = ((lane >> 3) & 1) * 8;
    unsigned ka_base = smem_u32(&Ks[brow][bcol]);
    unsigned va_base = smem_u32(&Vt[brow][bcol]);

    int r0 = i0 + w * 16 + gid, r1 = r0 + 8;
    float cA  = g_c[((size_t)r0 * kB + b) * kH + h];
    float cA1 = (r0 + 1 < kS) ? g_c[((size_t)(r0 + 1) * kB + b) * kH + h] : 0.f;
    float cB  = g_c[((size_t)r1 * kB + b) * kH + h];
    float cB1 = (r1 + 1 < kS) ? g_c[((size_t)(r1 + 1) * kB + b) * kH + h] : 0.f;

    float m0v = -1e30f, m1v = -1e30f, l0 = 0.f, l1 = 0.f;
    float o[8][4] = {};

    for (int j0 = 0; j0 < kS; j0 += 64) {
        __syncthreads();
        #pragma unroll
        for (int t = 0; t < 2; t++) {
            int idx = tid + t * 256;
            int r = idx >> 3, c = (idx & 7) * 8;
            *(float4*)&Ks[r][c] = *(const float4*)&g_k[kbase + (size_t)(j0 + r) * kDh + c];
            *(float4*)&Vt[r][c] = *(const float4*)&g_vt[vbase + (size_t)r * kS + j0 + c];
        }
        __syncthreads();

        // S = Q K^T  (per warp: 16 x 64)
        float s[8][4] = {};
        #pragma unroll
        for (int c4 = 0; c4 < 4; c4++) {          // kb = c4*16
            unsigned a[4];
            ldsm_x4(a, qa_base + c4 * 32);         // 16 halfs = 32B
            #pragma unroll
            for (int p = 0; p < 4; p++) {          // nt pair
                unsigned bb[4];
                ldsm_x4(bb, ka_base + (p * 16 * 72 + c4 * 16) * 2);
                mma16816(s[2 * p],     a, bb);
                mma16816(s[2 * p + 1], a, bb + 2);
            }
        }

        // BD + scale + online softmax (fp32), P packed to registers
        float rmax0 = -1e30f, rmax1 = -1e30f;
        #pragma unroll
        for (int nt = 0; nt < 8; nt++) {
            int gj = j0 + nt * 8 + tig * 2;
            float bd00 = (gj <= r0) ? cA : ((gj == r0 + 1) ? 0.f : cA1);
            float bd01 = (gj + 1 <= r0) ? cA : ((gj + 1 == r0 + 1) ? 0.f : cA1);
            float bd10 = (gj <= r1) ? cB : ((gj == r1 + 1) ? 0.f : cB1);
            float bd11 = (gj + 1 <= r1) ? cB : ((gj + 1 == r1 + 1) ? 0.f : cB1);
            s[nt][0] = (s[nt][0] + bd00) * kScale;
            s[nt][1] = (s[nt][1] + bd01) * kScale;
            s[nt][2] = (s[nt][2] + bd10) * kScale;
            s[nt][3] = (s[nt][3] + bd11) * kScale;
            rmax0 = fmaxf(rmax0, fmaxf(s[nt][0], s[nt][1]));
            rmax1 = fmaxf(rmax1, fmaxf(s[nt][2], s[nt][3]));
        }
        rmax0 = fmaxf(rmax0, __shfl_xor_sync(~0u, rmax0, 1));
        rmax0 = fmaxf(rmax0, __shfl_xor_sync(~0u, rmax0, 2));
        rmax1 = fmaxf(rmax1, __shfl_xor_sync(~0u, rmax1, 1));
        rmax1 = fmaxf(rmax1, __shfl_xor_sync(~0u, rmax1, 2));
        float mn0 = fmaxf(m0v, rmax0), mn1 = fmaxf(m1v, rmax1);
        float al0 = __expf(m0v - mn0), al1 = __expf(m1v - mn1);
        float rs0 = 0.f, rs1 = 0.f;
        unsigned ph0[8], ph1[8];
        #pragma unroll
        for (int nt = 0; nt < 8; nt++) {
            float p0 = __expf(s[nt][0] - mn0), p1 = __expf(s[nt][1] - mn0);
            float p2 = __expf(s[nt][2] - mn1), p3 = __expf(s[nt][3] - mn1);
            rs0 += p0 + p1; rs1 += p2 + p3;
            __half2 t0 = __floats2half2_rn(p0, p1);
            __half2 t1 = __floats2half2_rn(p2, p3);
            ph0[nt] = *(unsigned*)&t0;
            ph1[nt] = *(unsigned*)&t1;
        }
        rs0 += __shfl_xor_sync(~0u, rs0, 1);
        rs0 += __shfl_xor_sync(~0u, rs0, 2);
        rs1 += __shfl_xor_sync(~0u, rs1, 1);
        rs1 += __shfl_xor_sync(~0u, rs1, 2);
        l0 = l0 * al0 + rs0; l1 = l1 * al1 + rs1;
        m0v = mn0; m1v = mn1;
        #pragma unroll
        for (int nt = 0; nt < 8; nt++) {
            o[nt][0] *= al0; o[nt][1] *= al0;
            o[nt][2] *= al1; o[nt][3] *= al1;
        }

        // O += P V   (A from registers; B frags from Vt[d][j])
        #pragma unroll
        for (int c4 = 0; c4 < 4; c4++) {          // k-chunk = j tile c4*16
            unsigned a[4] = { ph0[2 * c4], ph1[2 * c4], ph0[2 * c4 + 1], ph1[2 * c4 + 1] };
            #pragma unroll
            for (int p = 0; p < 4; p++) {          // d pair tiles
                unsigned bb[4];
                ldsm_x4(bb, va_base + (p * 16 * 72 + c4 * 16) * 2);
                mma16816(o[2 * p],     a, bb);
                mma16816(o[2 * p + 1], a, bb + 2);
            }
        }
    }

    float inv0 = 1.f / l0, inv1 = 1.f / l1;
    #pragma unroll
    for (int nt = 0; nt < 8; nt++) {
        int d = nt * 8 + tig * 2;
        *(__half2*)&g_av[((size_t)r0 * kB + b) * kD + h * kDh + d] =
            __floats2half2_rn(o[nt][0] * inv0, o[nt][1] * inv0);
        *(__half2*)&g_av[((size_t)r1 * kB + b) * kD + h * kDh + d] =
            __floats2half2_rn(o[nt][2] * inv1, o[nt][3] * inv1);
    }
}

// ---------------------- Output GEMM + residual (fp16 mma) --------------------
__global__ __launch_bounds__(256) void gemm_out_kernel(float* __restrict__ out) {
    __shared__ __half As[2][128][40];
    __shared__ __half Bs[2][128][40];
    int tid = threadIdx.x, lane = tid & 31, w = tid >> 5;
    int gid = lane >> 2, tig = lane & 3;
    int m0 = blockIdx.y * 128, n0 = blockIdx.x * 128;
    int wm = w >> 2, wn = w & 3;
    constexpr unsigned stageB = 128 * 40 * 2;
    unsigned a_base = smem_u32(&As[0][wm * 64 + (lane & 15)][(lane >> 4) * 8]);
    unsigned b_base = smem_u32(&Bs[0][wn * 32 + (lane & 7) + ((lane >> 4) << 3)][((lane >> 3) & 1) * 8]);
    int lr = tid >> 2, lc = (tid & 3) * 8;
    int lr2 = lr + 64;
    float acc[4][4][4] = {};

    cp_async16(smem_u32(&As[0][lr][lc]),  &g_av[(size_t)(m0 + lr) * kD + lc]);
    cp_async16(smem_u32(&As[0][lr2][lc]), &g_av[(size_t)(m0 + lr2) * kD + lc]);
    cp_async16(smem_u32(&Bs[0][lr][lc]),  &g_wo_t[(size_t)(n0 + lr) * kD + lc]);
    cp_async16(smem_u32(&Bs[0][lr2][lc]), &g_wo_t[(size_t)(n0 + lr2) * kD + lc]);
    CP_COMMIT();

    constexpr int NIT = kD / 32;
    for (int it = 0; it < NIT; it++) {
        if (it + 1 < NIT) {
            int st = (it + 1) & 1, k0 = (it + 1) * 32;
            cp_async16(smem_u32(&As[st][lr][lc]),  &g_av[(size_t)(m0 + lr) * kD + k0 + lc]);
            cp_async16(smem_u32(&As[st][lr2][lc]), &g_av[(size_t)(m0 + lr2) * kD + k0 + lc]);
            cp_async16(smem_u32(&Bs[st][lr][lc]),  &g_wo_t[(size_t)(n0 + lr) * kD + k0 + lc]);
            cp_async16(smem_u32(&Bs[st][lr2][lc]), &g_wo_t[(size_t)(n0 + lr2) * kD + k0 + lc]);
            CP_COMMIT();
            CP_WAIT(1);
        } else {
            CP_WAIT(0);
        }
        __syncthreads();
        unsigned soff = (it & 1) * stageB;
        #pragma unroll
        for (int kb = 0; kb < 32; kb += 16) {
            unsigned a[4][4], b[2][4];
            #pragma unroll
            for (int mi = 0; mi < 4; mi++)
                ldsm_x4(a[mi], a_base + soff + (mi * 16 * 40 + kb) * 2);
            #pragma unroll
            for (int p = 0; p < 2; p++)
                ldsm_x4(b[p], b_base + soff + (p * 16 * 40 + kb) * 2);
            #pragma unroll
            for (int mi = 0; mi < 4; mi++)
                #pragma unroll
                for (int p = 0; p < 2; p++) {
                    mma16816(acc[mi][2 * p],     a[mi], b[p]);
                    mma16816(acc[mi][2 * p + 1], a[mi], b[p] + 2);
                }
        }
        __syncthreads();
    }
    #pragma unroll
    for (int mi = 0; mi < 4; mi++) {
        int r0e = m0 + wm * 64 + mi * 16 + gid, r1e = r0e + 8;
        #pragma unroll
        for (int ni = 0; ni < 4; ni++) {
            int c0 = n0 + wn * 32 + ni * 8 + tig * 2;
            float2 x0 = *(const float2*)&g_xn[(size_t)r0e * kD + c0];
            float2 x1 = *(const float2*)&g_xn[(size_t)r1e * kD + c0];
            float2 o0 = { acc[mi][ni][0] + x0.x, acc[mi][ni][1] + x0.y };
            float2 o1 = { acc[mi][ni][2] + x1.x, acc[mi][ni][3] + x1.y };
            *(float2*)&out[(size_t)r0e * kD + c0] = o0;
            *(float2*)&out[(size_t)r1e * kD + c0] = o1;
        }
    }
}

// --------------------------------- launch ------------------------------------
extern "C" void kernel_launch(void* const* d_in, const int* in_sizes, int n_in,
                              void* d_out, int out_size) {
    const float* x    = (const float*)d_in[0];
    const float* r    = (const float*)d_in[1];
    const float* rw   = (const float*)d_in[2];
    const float* rr   = (const float*)d_in[3];
    const float* ln_g = (const float*)d_in[4];
    const float* ln_b = (const float*)d_in[5];
    const float* Wqkv = (const float*)d_in[6];
    const float* Wr   = (const float*)d_in[7];
    const float* Wo   = (const float*)d_in[8];
    float* out = (float*)d_out;

    ln_kernel<<<kRows, 256>>>(x, ln_g, ln_b);
    convw_kernel<0><<<dim3(3 * kD / 32, kD / 32), dim3(32, 8)>>>(Wqkv);
    convw_kernel<1><<<dim3(kD / 32, kD / 32), dim3(32, 8)>>>(Wo);
    rk0_part_kernel<<<dim3(kD / 256, kRkChunks), 256>>>(r, Wr);
    rk0_reduce_kernel<<<kD / 256, 256>>>();
    gemm_qkv_kernel<<<dim3(3 * kD / 128, kRows / 128), 256>>>(rw);
    cbd_kernel<<<kS * kB * kH / 8, 256>>>(rw, rr);
    flash_kernel<<<dim3(kS / 128, kH, kB), 256>>>();
    gemm_out_kernel<<<dim3(kD / 128, kRows / 128), 256>>>(out);
}

// round 11
// speedup vs baseline: 6.1540x; 1.0641x over previous
#include <cuda_runtime.h>
#include <cuda_fp16.h>
#include <math.h>

namespace {
constexpr int kS = 2048, kB = 2, kD = 1024, kH = 16, kDh = 64;
constexpr int kRows = kS * kB;            // 4096
constexpr float kScale = 0.125f;          // 1/sqrt(64)
constexpr float kEps = 1e-5f;
constexpr int kRkChunks = 16;
}

// ------------------------- scratch (static device memory) -------------------
// NOTE: only referenced inside device code — never passed as kernel args.
__device__ float  g_xn[kRows * kD];
__device__ __half g_xn_h[kRows * kD];
__device__ __half g_wqkv_t[3 * kD * kD];           // Wqkv^T [n][k]
__device__ __half g_wo_t[kD * kD];                 // Wo^T [n][k]
__device__ __half g_q[kB * kH * kS * kDh];         // q + rw [b][h][s][d]
__device__ __half g_k[kB * kH * kS * kDh];         // [b][h][s][d]
__device__ __half g_v[kB * kH * kS * kDh];         // [b][h][s][d] (natural)
__device__ __half g_av[kRows * kD];
__device__ float  g_rk0p[kRkChunks * kD];
__device__ float  g_rk0[kD];
__device__ float  g_c[kS * kB * kH];

// ------------------------------ asm helpers ----------------------------------
__device__ __forceinline__ void mma16816(float* c, const unsigned* a, const unsigned* b) {
    asm volatile(
        "mma.sync.aligned.m16n8k16.row.col.f32.f16.f16.f32 "
        "{%0,%1,%2,%3},{%4,%5,%6,%7},{%8,%9},{%0,%1,%2,%3};\n"
        : "+f"(c[0]), "+f"(c[1]), "+f"(c[2]), "+f"(c[3])
        : "r"(a[0]), "r"(a[1]), "r"(a[2]), "r"(a[3]), "r"(b[0]), "r"(b[1]));
}
__device__ __forceinline__ void ldsm_x4(unsigned* r, unsigned addr) {
    asm volatile("ldmatrix.sync.aligned.m8n8.x4.shared.b16 {%0,%1,%2,%3}, [%4];\n"
                 : "=r"(r[0]), "=r"(r[1]), "=r"(r[2]), "=r"(r[3]) : "r"(addr));
}
__device__ __forceinline__ void ldsm_x4_trans(unsigned* r, unsigned addr) {
    asm volatile("ldmatrix.sync.aligned.m8n8.x4.trans.shared.b16 {%0,%1,%2,%3}, [%4];\n"
                 : "=r"(r[0]), "=r"(r[1]), "=r"(r[2]), "=r"(r[3]) : "r"(addr));
}
__device__ __forceinline__ unsigned smem_u32(const void* p) {
    return (unsigned)__cvta_generic_to_shared(p);
}
__device__ __forceinline__ void cp_async16(unsigned dst, const void* src) {
    asm volatile("cp.async.ca.shared.global [%0], [%1], 16;\n"
                 :: "r"(dst), "l"(__cvta_generic_to_global(src)));
}
#define CP_COMMIT() asm volatile("cp.async.commit_group;\n")
#define CP_WAIT(n)  asm volatile("cp.async.wait_group %0;\n" :: "n"(n))

// ------------------------------ LayerNorm -----------------------------------
__global__ void ln_kernel(const float* __restrict__ x,
                          const float* __restrict__ gamma,
                          const float* __restrict__ beta) {
    int row = blockIdx.x;
    int t = threadIdx.x;
    const float4 v = reinterpret_cast<const float4*>(x + (size_t)row * kD)[t];
    float s1 = v.x + v.y + v.z + v.w;
    float s2 = v.x*v.x + v.y*v.y + v.z*v.z + v.w*v.w;
    #pragma unroll
    for (int o = 16; o; o >>= 1) {
        s1 += __shfl_xor_sync(~0u, s1, o);
        s2 += __shfl_xor_sync(~0u, s2, o);
    }
    __shared__ float sm1[8], sm2[8];
    int w = t >> 5, lane = t & 31;
    if (lane == 0) { sm1[w] = s1; sm2[w] = s2; }
    __syncthreads();
    if (w == 0) {
        s1 = (lane < 8) ? sm1[lane] : 0.f;
        s2 = (lane < 8) ? sm2[lane] : 0.f;
        #pragma unroll
        for (int o = 4; o; o >>= 1) {
            s1 += __shfl_xor_sync(~0u, s1, o);
            s2 += __shfl_xor_sync(~0u, s2, o);
        }
        if (lane == 0) { sm1[0] = s1; sm2[0] = s2; }
    }
    __syncthreads();
    float mu = sm1[0] * (1.f / kD);
    float var = sm2[0] * (1.f / kD) - mu * mu;
    float rstd = rsqrtf(var + kEps);
    const float4 gv = reinterpret_cast<const float4*>(gamma)[t];
    const float4 bv = reinterpret_cast<const float4*>(beta)[t];
    float4 o;
    o.x = (v.x - mu) * rstd * gv.x + bv.x;
    o.y = (v.y - mu) * rstd * gv.y + bv.y;
    o.z = (v.z - mu) * rstd * gv.z + bv.z;
    o.w = (v.w - mu) * rstd * gv.w + bv.w;
    reinterpret_cast<float4*>(g_xn + (size_t)row * kD)[t] = o;
    *reinterpret_cast<__half2*>(&g_xn_h[(size_t)row * kD + t * 4])     = __floats2half2_rn(o.x, o.y);
    *reinterpret_cast<__half2*>(&g_xn_h[(size_t)row * kD + t * 4 + 2]) = __floats2half2_rn(o.z, o.w);
}

// --------------- weight transpose + fp32 -> fp16 conversion ------------------
template <int WHICH>
__global__ void convw_kernel(const float* __restrict__ src) {
    constexpr int K = kD;
    constexpr int N = (WHICH == 0) ? 3 * kD : kD;
    __half* dst = (WHICH == 0) ? g_wqkv_t : g_wo_t;
    __shared__ float tile[32][33];
    int n0 = blockIdx.x * 32, k0 = blockIdx.y * 32;
    int tx = threadIdx.x, ty = threadIdx.y;
    #pragma unroll
    for (int i = 0; i < 32; i += 8)
        tile[ty + i][tx] = src[(size_t)(k0 + ty + i) * N + n0 + tx];
    __syncthreads();
    #pragma unroll
    for (int i = 0; i < 32; i += 8)
        dst[(size_t)(n0 + ty + i) * K + k0 + tx] = __float2half(tile[tx][ty + i]);
}

// ----------------------------- rk0 = r @ Wr (k-split) ------------------------
__global__ void rk0_part_kernel(const float* __restrict__ r, const float* __restrict__ Wr) {
    int col = blockIdx.x * 256 + threadIdx.x;
    int chunk = blockIdx.y;
    int d0 = chunk * (kD / kRkChunks);
    float s = 0.f;
    #pragma unroll
    for (int i = 0; i < kD / kRkChunks; i++)
        s += r[d0 + i] * Wr[(size_t)(d0 + i) * kD + col];
    g_rk0p[chunk * kD + col] = s;
}
__global__ void rk0_reduce_kernel() {
    int col = blockIdx.x * 256 + threadIdx.x;
    float s = 0.f;
    #pragma unroll
    for (int c = 0; c < kRkChunks; c++) s += g_rk0p[c * kD + col];
    g_rk0[col] = s;
}

// ------------------------------ QKV GEMM (fp16 mma, cp.async + ldmatrix) -----
__global__ __launch_bounds__(256) void gemm_qkv_kernel(const float* __restrict__ rw) {
    __shared__ __half As[2][128][40];
    __shared__ __half Bs[2][128][40];
    int tid = threadIdx.x, lane = tid & 31, w = tid >> 5;
    int gid = lane >> 2, tig = lane & 3;
    int m0 = blockIdx.y * 128, n0 = blockIdx.x * 128;
    int wm = w >> 2, wn = w & 3;
    constexpr unsigned stageB = 128 * 40 * 2;
    unsigned a_base = smem_u32(&As[0][wm * 64 + (lane & 15)][(lane >> 4) * 8]);
    unsigned b_base = smem_u32(&Bs[0][wn * 32 + (lane & 7) + ((lane >> 4) << 3)][((lane >> 3) & 1) * 8]);
    int lr = tid >> 2, lc = (tid & 3) * 8;
    int lr2 = lr + 64;
    float acc[4][4][4] = {};

    cp_async16(smem_u32(&As[0][lr][lc]),  &g_xn_h[(size_t)(m0 + lr) * kD + lc]);
    cp_async16(smem_u32(&As[0][lr2][lc]), &g_xn_h[(size_t)(m0 + lr2) * kD + lc]);
    cp_async16(smem_u32(&Bs[0][lr][lc]),  &g_wqkv_t[(size_t)(n0 + lr) * kD + lc]);
    cp_async16(smem_u32(&Bs[0][lr2][lc]), &g_wqkv_t[(size_t)(n0 + lr2) * kD + lc]);
    CP_COMMIT();

    constexpr int NIT = kD / 32;
    for (int it = 0; it < NIT; it++) {
        if (it + 1 < NIT) {
            int st = (it + 1) & 1, k0 = (it + 1) * 32;
            cp_async16(smem_u32(&As[st][lr][lc]),  &g_xn_h[(size_t)(m0 + lr) * kD + k0 + lc]);
            cp_async16(smem_u32(&As[st][lr2][lc]), &g_xn_h[(size_t)(m0 + lr2) * kD + k0 + lc]);
            cp_async16(smem_u32(&Bs[st][lr][lc]),  &g_wqkv_t[(size_t)(n0 + lr) * kD + k0 + lc]);
            cp_async16(smem_u32(&Bs[st][lr2][lc]), &g_wqkv_t[(size_t)(n0 + lr2) * kD + k0 + lc]);
            CP_COMMIT();
            CP_WAIT(1);
        } else {
            CP_WAIT(0);
        }
        __syncthreads();
        unsigned soff = (it & 1) * stageB;
        #pragma unroll
        for (int kb = 0; kb < 32; kb += 16) {
            unsigned a[4][4], b[2][4];
            #pragma unroll
            for (int mi = 0; mi < 4; mi++)
                ldsm_x4(a[mi], a_base + soff + (mi * 16 * 40 + kb) * 2);
            #pragma unroll
            for (int p = 0; p < 2; p++)
                ldsm_x4(b[p], b_base + soff + (p * 16 * 40 + kb) * 2);
            #pragma unroll
            for (int mi = 0; mi < 4; mi++)
                #pragma unroll
                for (int p = 0; p < 2; p++) {
                    mma16816(acc[mi][2 * p],     a[mi], b[p]);
                    mma16816(acc[mi][2 * p + 1], a[mi], b[p] + 2);
                }
        }
        __syncthreads();
    }
    // epilogue: scatter to q/k/v (all coalesced __half2)
    #pragma unroll
    for (int mi = 0; mi < 4; mi++) {
        int r0e = m0 + wm * 64 + mi * 16 + gid, r1e = r0e + 8;
        int s0 = r0e >> 1, b0e = r0e & 1;
        int s1 = r1e >> 1, b1e = r1e & 1;
        #pragma unroll
        for (int ni = 0; ni < 4; ni++) {
            int c0 = n0 + wn * 32 + ni * 8 + tig * 2;
            int part = c0 >> 10, rem = c0 & 1023, hh = rem >> 6, d = rem & 63;
            size_t di0 = (((size_t)(b0e * kH + hh)) * kS + s0) * kDh + d;
            size_t di1 = (((size_t)(b1e * kH + hh)) * kS + s1) * kDh + d;
            float v00 = acc[mi][ni][0], v01 = acc[mi][ni][1];
            float v10 = acc[mi][ni][2], v11 = acc[mi][ni][3];
            if (part == 0) {
                float w0 = rw[rem], w1 = rw[rem + 1];
                *(__half2*)&g_q[di0] = __floats2half2_rn(v00 + w0, v01 + w1);
                *(__half2*)&g_q[di1] = __floats2half2_rn(v10 + w0, v11 + w1);
            } else if (part == 1) {
                *(__half2*)&g_k[di0] = __floats2half2_rn(v00, v01);
                *(__half2*)&g_k[di1] = __floats2half2_rn(v10, v11);
            } else {
                *(__half2*)&g_v[di0] = __floats2half2_rn(v00, v01);
                *(__half2*)&g_v[di1] = __floats2half2_rn(v10, v11);
            }
        }
    }
}

// ----------------- BD constants: c[i,b,h] = (q + rr)·rk0 ---------------------
__global__ void cbd_kernel(const float* __restrict__ rw, const float* __restrict__ rr) {
    int warp = blockIdx.x * 8 + (threadIdx.x >> 5);
    int lane = threadIdx.x & 31;
    int h = warp & 15, bb = (warp >> 4) & 1, i = warp >> 5;
    float s = 0.f;
    #pragma unroll
    for (int t = 0; t < 2; t++) {
        int d = lane + t * 32;
        size_t qi = (((size_t)(bb * kH + h)) * kS + i) * kDh + d;
        int hd = h * kDh + d;
        s += (__half2float(g_q[qi]) - rw[hd] + rr[hd]) * g_rk0[hd];
    }
    #pragma unroll
    for (int o = 16; o; o >>= 1) s += __shfl_xor_sync(~0u, s, o);
    if (lane == 0) g_c[((size_t)i * kB + bb) * kH + h] = s;
}

// ------------------- Flash attention (fp16 mma, 128q, reg-Q/P, cp.async) -----
// Block: 256 thr = 8 warps, one (b,h), 128 query rows (16/warp), key tiles 64.
__global__ __launch_bounds__(256) void flash_kernel() {
    __shared__ __half Ks[2][64][72];
    __shared__ __half Vs[2][64][72];       // natural [j][d]
    int b = blockIdx.z, h = blockIdx.y, i0 = blockIdx.x * 128;
    int tid = threadIdx.x, w = tid >> 5, lane = tid & 31;
    int gid = lane >> 2, tig = lane & 3;
    size_t base = ((size_t)(b * kH + h)) * kS * kDh;

    // ---- stage Q through the K buffer (128 rows x 72 stride), ldsm to regs --
    __half* qstage = &Ks[0][0][0];
    #pragma unroll
    for (int t = 0; t < 4; t++) {
        int idx = tid + t * 256;
        int r = idx >> 3, c = (idx & 7) * 8;
        *(float4*)&qstage[r * 72 + c] = *(const float4*)&g_q[base + (size_t)(i0 + r) * kDh + c];
    }
    __syncthreads();
    unsigned qf[4][4];
    {
        unsigned qa = smem_u32(qstage + (w * 16 + (lane & 15)) * 72 + (lane >> 4) * 8);
        #pragma unroll
        for (int c4 = 0; c4 < 4; c4++) ldsm_x4(qf[c4], qa + c4 * 32);
    }
    __syncthreads();   // Q captured; K buffer reusable

    // fragment bases (stage 0)
    unsigned ka_base = smem_u32(&Ks[0][(lane & 7) + ((lane >> 4) << 3)][((lane >> 3) & 1) * 8]);
    unsigned va_base = smem_u32(&Vs[0][(lane & 7) + (((lane >> 3) & 1) << 3)][(lane >> 4) * 8]);
    constexpr unsigned stageB = 64 * 72 * 2;

    int r0 = i0 + w * 16 + gid, r1 = r0 + 8;
    float cA  = g_c[((size_t)r0 * kB + b) * kH + h];
    float cA1 = (r0 + 1 < kS) ? g_c[((size_t)(r0 + 1) * kB + b) * kH + h] : 0.f;
    float cB  = g_c[((size_t)r1 * kB + b) * kH + h];
    float cB1 = (r1 + 1 < kS) ? g_c[((size_t)(r1 + 1) * kB + b) * kH + h] : 0.f;

    float m0v = -1e30f, m1v = -1e30f, l0 = 0.f, l1 = 0.f;
    float o[8][4] = {};

    // pipeline loader: 64 rows x 64 halfs = 512 chunks/array; 256 thr x 2 chunks
    int plr = tid >> 2, plc = (tid & 3) * 8;   // + second chunk at plc+32
    cp_async16(smem_u32(&Ks[0][plr][plc]),      &g_k[base + (size_t)plr * kDh + plc]);
    cp_async16(smem_u32(&Ks[0][plr][plc + 32]), &g_k[base + (size_t)plr * kDh + plc + 32]);
    cp_async16(smem_u32(&Vs[0][plr][plc]),      &g_v[base + (size_t)plr * kDh + plc]);
    cp_async16(smem_u32(&Vs[0][plr][plc + 32]), &g_v[base + (size_t)plr * kDh + plc + 32]);
    CP_COMMIT();

    constexpr int NT = kS / 64;
    for (int jt = 0; jt < NT; jt++) {
        if (jt + 1 < NT) {
            int st = (jt + 1) & 1;
            size_t roff = base + (size_t)((jt + 1) * 64 + plr) * kDh + plc;
            cp_async16(smem_u32(&Ks[st][plr][plc]),      &g_k[roff]);
            cp_async16(smem_u32(&Ks[st][plr][plc + 32]), &g_k[roff + 32]);
            cp_async16(smem_u32(&Vs[st][plr][plc]),      &g_v[roff]);
            cp_async16(smem_u32(&Vs[st][plr][plc + 32]), &g_v[roff + 32]);
            CP_COMMIT();
            CP_WAIT(1);
        } else {
            CP_WAIT(0);
        }
        __syncthreads();
        unsigned soff = (jt & 1) * stageB;
        int j0 = jt * 64;

        // S = Q K^T  (per warp: 16 x 64)
        float s[8][4] = {};
        #pragma unroll
        for (int c4 = 0; c4 < 4; c4++) {
            #pragma unroll
            for (int p = 0; p < 4; p++) {
                unsigned bb[4];
                ldsm_x4(bb, ka_base + soff + (p * 16 * 72 + c4 * 16) * 2);
                mma16816(s[2 * p],     qf[c4], bb);
                mma16816(s[2 * p + 1], qf[c4], bb + 2);
            }
        }

        // BD + scale + online softmax (fp32), P packed to registers
        float rmax0 = -1e30f, rmax1 = -1e30f;
        #pragma unroll
        for (int nt = 0; nt < 8; nt++) {
            int gj = j0 + nt * 8 + tig * 2;
            float bd00 = (gj <= r0) ? cA : ((gj == r0 + 1) ? 0.f : cA1);
            float bd01 = (gj + 1 <= r0) ? cA : ((gj + 1 == r0 + 1) ? 0.f : cA1);
            float bd10 = (gj <= r1) ? cB : ((gj == r1 + 1) ? 0.f : cB1);
            float bd11 = (gj + 1 <= r1) ? cB : ((gj + 1 == r1 + 1) ? 0.f : cB1);
            s[nt][0] = (s[nt][0] + bd00) * kScale;
            s[nt][1] = (s[nt][1] + bd01) * kScale;
            s[nt][2] = (s[nt][2] + bd10) * kScale;
            s[nt][3] = (s[nt][3] + bd11) * kScale;
            rmax0 = fmaxf(rmax0, fmaxf(s[nt][0], s[nt][1]));
            rmax1 = fmaxf(rmax1, fmaxf(s[nt][2], s[nt][3]));
        }
        rmax0 = fmaxf(rmax0, __shfl_xor_sync(~0u, rmax0, 1));
        rmax0 = fmaxf(rmax0, __shfl_xor_sync(~0u, rmax0, 2));
        rmax1 = fmaxf(rmax1, __shfl_xor_sync(~0u, rmax1, 1));
        rmax1 = fmaxf(rmax1, __shfl_xor_sync(~0u, rmax1, 2));
        float mn0 = fmaxf(m0v, rmax0), mn1 = fmaxf(m1v, rmax1);
        float al0 = __expf(m0v - mn0), al1 = __expf(m1v - mn1);
        float rs0 = 0.f, rs1 = 0.f;
        unsigned ph0[8], ph1[8];
        #pragma unroll
        for (int nt = 0; nt < 8; nt++) {
            float p0 = __expf(s[nt][0] - mn0), p1 = __expf(s[nt][1] - mn0);
            float p2 = __expf(s[nt][2] - mn1), p3 = __expf(s[nt][3] - mn1);
            rs0 += p0 + p1; rs1 += p2 + p3;
            __half2 t0 = __floats2half2_rn(p0, p1);
            __half2 t1 = __floats2half2_rn(p2, p3);
            ph0[nt] = *(unsigned*)&t0;
            ph1[nt] = *(unsigned*)&t1;
        }
        rs0 += __shfl_xor_sync(~0u, rs0, 1);
        rs0 += __shfl_xor_sync(~0u, rs0, 2);
        rs1 += __shfl_xor_sync(~0u, rs1, 1);
        rs1 += __shfl_xor_sync(~0u, rs1, 2);
        l0 = l0 * al0 + rs0; l1 = l1 * al1 + rs1;
        m0v = mn0; m1v = mn1;
        #pragma unroll
        for (int nt = 0; nt < 8; nt++) {
            o[nt][0] *= al0; o[nt][1] *= al0;
            o[nt][2] *= al1; o[nt][3] *= al1;
        }

        // O += P V   (A from regs; B via ldmatrix.trans on natural V[j][d])
        #pragma unroll
        for (int c4 = 0; c4 < 4; c4++) {
            unsigned a[4] = { ph0[2 * c4], ph1[2 * c4], ph0[2 * c4 + 1], ph1[2 * c4 + 1] };
            #pragma unroll
            for (int p = 0; p < 4; p++) {
                unsigned bb[4];
                ldsm_x4_trans(bb, va_base + soff + (c4 * 16 * 72 + p * 16) * 2);
                mma16816(o[2 * p],     a, bb);
                mma16816(o[2 * p + 1], a, bb + 2);
            }
        }
        __syncthreads();
    }

    float inv0 = 1.f / l0, inv1 = 1.f / l1;
    #pragma unroll
    for (int nt = 0; nt < 8; nt++) {
        int d = nt * 8 + tig * 2;
        *(__half2*)&g_av[((size_t)r0 * kB + b) * kD + h * kDh + d] =
            __floats2half2_rn(o[nt][0] * inv0, o[nt][1] * inv0);
        *(__half2*)&g_av[((size_t)r1 * kB + b) * kD + h * kDh + d] =
            __floats2half2_rn(o[nt][2] * inv1, o[nt][3] * inv1);
    }
}

// ---------------------- Output GEMM + residual (fp16 mma) --------------------
__global__ __launch_bounds__(256) void gemm_out_kernel(float* __restrict__ out) {
    __shared__ __half As[2][128][40];
    __shared__ __half Bs[2][128][40];
    int tid = threadIdx.x, lane = tid & 31, w = tid >> 5;
    int gid = lane >> 2, tig = lane & 3;
    int m0 = blockIdx.y * 128, n0 = blockIdx.x * 128;
    int wm = w >> 2, wn = w & 3;
    constexpr unsigned stageB = 128 * 40 * 2;
    unsigned a_base = smem_u32(&As[0][wm * 64 + (lane & 15)][(lane >> 4) * 8]);
    unsigned b_base = smem_u32(&Bs[0][wn * 32 + (lane & 7) + ((lane >> 4) << 3)][((lane >> 3) & 1) * 8]);
    int lr = tid >> 2, lc = (tid & 3) * 8;
    int lr2 = lr + 64;
    float acc[4][4][4] = {};

    cp_async16(smem_u32(&As[0][lr][lc]),  &g_av[(size_t)(m0 + lr) * kD + lc]);
    cp_async16(smem_u32(&As[0][lr2][lc]), &g_av[(size_t)(m0 + lr2) * kD + lc]);
    cp_async16(smem_u32(&Bs[0][lr][lc]),  &g_wo_t[(size_t)(n0 + lr) * kD + lc]);
    cp_async16(smem_u32(&Bs[0][lr2][lc]), &g_wo_t[(size_t)(n0 + lr2) * kD + lc]);
    CP_COMMIT();

    constexpr int NIT = kD / 32;
    for (int it = 0; it < NIT; it++) {
        if (it + 1 < NIT) {
            int st = (it + 1) & 1, k0 = (it + 1) * 32;
            cp_async16(smem_u32(&As[st][lr][lc]),  &g_av[(size_t)(m0 + lr) * kD + k0 + lc]);
            cp_async16(smem_u32(&As[st][lr2][lc]), &g_av[(size_t)(m0 + lr2) * kD + k0 + lc]);
            cp_async16(smem_u32(&Bs[st][lr][lc]),  &g_wo_t[(size_t)(n0 + lr) * kD + k0 + lc]);
            cp_async16(smem_u32(&Bs[st][lr2][lc]), &g_wo_t[(size_t)(n0 + lr2) * kD + k0 + lc]);
            CP_COMMIT();
            CP_WAIT(1);
        } else {
            CP_WAIT(0);
        }
        __syncthreads();
        unsigned soff = (it & 1) * stageB;
        #pragma unroll
        for (int kb = 0; kb < 32; kb += 16) {
            unsigned a[4][4], b[2][4];
            #pragma unroll
            for (int mi = 0; mi < 4; mi++)
                ldsm_x4(a[mi], a_base + soff + (mi * 16 * 40 + kb) * 2);
            #pragma unroll
            for (int p = 0; p < 2; p++)
                ldsm_x4(b[p], b_base + soff + (p * 16 * 40 + kb) * 2);
            #pragma unroll
            for (int mi = 0; mi < 4; mi++)
                #pragma unroll
                for (int p = 0; p < 2; p++) {
                    mma16816(acc[mi][2 * p],     a[mi], b[p]);
                    mma16816(acc[mi][2 * p + 1], a[mi], b[p] + 2);
                }
        }
        __syncthreads();
    }
    #pragma unroll
    for (int mi = 0; mi < 4; mi++) {
        int r0e = m0 + wm * 64 + mi * 16 + gid, r1e = r0e + 8;
        #pragma unroll
        for (int ni = 0; ni < 4; ni++) {
            int c0 = n0 + wn * 32 + ni * 8 + tig * 2;
            float2 x0 = *(const float2*)&g_xn[(size_t)r0e * kD + c0];
            float2 x1 = *(const float2*)&g_xn[(size_t)r1e * kD + c0];
            float2 o0 = { acc[mi][ni][0] + x0.x, acc[mi][ni][1] + x0.y };
            float2 o1 = { acc[mi][ni][2] + x1.x, acc[mi][ni][3] + x1.y };
            *(float2*)&out[(size_t)r0e * kD + c0] = o0;
            *(float2*)&out[(size_t)r1e * kD + c0] = o1;
        }
    }
}

// --------------------------------- launch ------------------------------------
extern "C" void kernel_launch(void* const* d_in, const int* in_sizes, int n_in,
                              void* d_out, int out_size) {
    const float* x    = (const float*)d_in[0];
    const float* r    = (const float*)d_in[1];
    const float* rw   = (const float*)d_in[2];
    const float* rr   = (const float*)d_in[3];
    const float* ln_g = (const float*)d_in[4];
    const float* ln_b = (const float*)d_in[5];
    const float* Wqkv = (const float*)d_in[6];
    const float* Wr   = (const float*)d_in[7];
    const float* Wo   = (const float*)d_in[8];
    float* out = (float*)d_out;

    ln_kernel<<<kRows, 256>>>(x, ln_g, ln_b);
    convw_kernel<0><<<dim3(3 * kD / 32, kD / 32), dim3(32, 8)>>>(Wqkv);
    convw_kernel<1><<<dim3(kD / 32, kD / 32), dim3(32, 8)>>>(Wo);
    rk0_part_kernel<<<dim3(kD / 256, kRkChunks), 256>>>(r, Wr);
    rk0_reduce_kernel<<<kD / 256, 256>>>();
    gemm_qkv_kernel<<<dim3(3 * kD / 128, kRows / 128), 256>>>(rw);
    cbd_kernel<<<kS * kB * kH / 8, 256>>>(rw, rr);
    flash_kernel<<<dim3(kS / 128, kH, kB), 256>>>();
    gemm_out_kernel<<<dim3(kD / 128, kRows / 128), 256>>>(out);
}

// round 13
// speedup vs baseline: 6.3917x; 1.0386x over previous
#include <cuda_runtime.h>
#include <cuda_fp16.h>
#include <math.h>

namespace {
constexpr int kS = 2048, kB = 2, kD = 1024, kH = 16, kDh = 64;
constexpr int kRows = kS * kB;            // 4096
constexpr float kScale = 0.125f;          // 1/sqrt(64)
constexpr float kEps = 1e-5f;
constexpr int kRkChunks = 16;
// prologue block ranges
constexpr int kNbLn  = kRows;                       // 4096
constexpr int kNbCw0 = (3 * kD / 32) * (kD / 32);   // 3072
constexpr int kNbCw1 = (kD / 32) * (kD / 32);       // 1024
constexpr int kNbRk  = (kD / 256) * kRkChunks;      // 64
}

// ------------------------- scratch (static device memory) -------------------
// NOTE: only referenced inside device code — never passed as kernel args.
__device__ float  g_xn[kRows * kD];
__device__ __half g_xn_h[kRows * kD];
__device__ __half g_wqkv_t[3 * kD * kD];           // Wqkv^T [n][k]
__device__ __half g_wo_t[kD * kD];                 // Wo^T [n][k]
__device__ __half g_q[kB * kH * kS * kDh];         // q + rw [b][h][s][d]
__device__ __half g_k[kB * kH * kS * kDh];         // [b][h][s][d]
__device__ __half g_v[kB * kH * kS * kDh];         // [b][h][s][d]
__device__ __half g_av[kRows * kD];
__device__ float  g_rk0p[kRkChunks * kD];
__device__ float  g_rk0[kD];

// ------------------------------ asm helpers ----------------------------------
__device__ __forceinline__ void mma16816(float* c, const unsigned* a, const unsigned* b) {
    asm volatile(
        "mma.sync.aligned.m16n8k16.row.col.f32.f16.f16.f32 "
        "{%0,%1,%2,%3},{%4,%5,%6,%7},{%8,%9},{%0,%1,%2,%3};\n"
        : "+f"(c[0]), "+f"(c[1]), "+f"(c[2]), "+f"(c[3])
        : "r"(a[0]), "r"(a[1]), "r"(a[2]), "r"(a[3]), "r"(b[0]), "r"(b[1]));
}
__device__ __forceinline__ void ldsm_x4(unsigned* r, unsigned addr) {
    asm volatile("ldmatrix.sync.aligned.m8n8.x4.shared.b16 {%0,%1,%2,%3}, [%4];\n"
                 : "=r"(r[0]), "=r"(r[1]), "=r"(r[2]), "=r"(r[3]) : "r"(addr));
}
__device__ __forceinline__ void ldsm_x4_trans(unsigned* r, unsigned addr) {
    asm volatile("ldmatrix.sync.aligned.m8n8.x4.trans.shared.b16 {%0,%1,%2,%3}, [%4];\n"
                 : "=r"(r[0]), "=r"(r[1]), "=r"(r[2]), "=r"(r[3]) : "r"(addr));
}
__device__ __forceinline__ unsigned smem_u32(const void* p) {
    return (unsigned)__cvta_generic_to_shared(p);
}
__device__ __forceinline__ void cp_async16(unsigned dst, const void* src) {
    asm volatile("cp.async.cg.shared.global [%0], [%1], 16;\n"
                 :: "r"(dst), "l"(__cvta_generic_to_global(src)));
}
#define CP_COMMIT() asm volatile("cp.async.commit_group;\n")
#define CP_WAIT(n)  asm volatile("cp.async.wait_group %0;\n" :: "n"(n))

// ------------------- fused prologue: ln | convw0 | convw1 | rk0_part ---------
__global__ __launch_bounds__(256) void prologue_kernel(
        const float* __restrict__ x, const float* __restrict__ gamma,
        const float* __restrict__ beta, const float* __restrict__ Wqkv,
        const float* __restrict__ Wo, const float* __restrict__ r,
        const float* __restrict__ Wr) {
    __shared__ float tile[32][33];
    __shared__ float sm1[8], sm2[8];
    int blk = blockIdx.x;
    int tid = threadIdx.x;

    if (blk < kNbLn) {
        // ---------------- LayerNorm ----------------
        int row = blk, t = tid;
        const float4 v = reinterpret_cast<const float4*>(x + (size_t)row * kD)[t];
        float s1 = v.x + v.y + v.z + v.w;
        float s2 = v.x*v.x + v.y*v.y + v.z*v.z + v.w*v.w;
        #pragma unroll
        for (int o = 16; o; o >>= 1) {
            s1 += __shfl_xor_sync(~0u, s1, o);
            s2 += __shfl_xor_sync(~0u, s2, o);
        }
        int w = t >> 5, lane = t & 31;
        if (lane == 0) { sm1[w] = s1; sm2[w] = s2; }
        __syncthreads();
        if (w == 0) {
            s1 = (lane < 8) ? sm1[lane] : 0.f;
            s2 = (lane < 8) ? sm2[lane] : 0.f;
            #pragma unroll
            for (int o = 4; o; o >>= 1) {
                s1 += __shfl_xor_sync(~0u, s1, o);
                s2 += __shfl_xor_sync(~0u, s2, o);
            }
            if (lane == 0) { sm1[0] = s1; sm2[0] = s2; }
        }
        __syncthreads();
        float mu = sm1[0] * (1.f / kD);
        float var = sm2[0] * (1.f / kD) - mu * mu;
        float rstd = rsqrtf(var + kEps);
        const float4 gv = reinterpret_cast<const float4*>(gamma)[t];
        const float4 bv = reinterpret_cast<const float4*>(beta)[t];
        float4 o;
        o.x = (v.x - mu) * rstd * gv.x + bv.x;
        o.y = (v.y - mu) * rstd * gv.y + bv.y;
        o.z = (v.z - mu) * rstd * gv.z + bv.z;
        o.w = (v.w - mu) * rstd * gv.w + bv.w;
        reinterpret_cast<float4*>(g_xn + (size_t)row * kD)[t] = o;
        *reinterpret_cast<__half2*>(&g_xn_h[(size_t)row * kD + t * 4])     = __floats2half2_rn(o.x, o.y);
        *reinterpret_cast<__half2*>(&g_xn_h[(size_t)row * kD + t * 4 + 2]) = __floats2half2_rn(o.z, o.w);
    } else if (blk < kNbLn + kNbCw0 + kNbCw1) {
        // ---------------- weight transpose + cast ----------------
        bool first = (blk < kNbLn + kNbCw0);
        int local = first ? (blk - kNbLn) : (blk - kNbLn - kNbCw0);
        int N = first ? 3 * kD : kD;
        const float* src = first ? Wqkv : Wo;
        __half* dst = first ? g_wqkv_t : g_wo_t;
        int nt = N / 32;
        int bx = local % nt, by = local / nt;
        int n0 = bx * 32, k0 = by * 32;
        int tx = tid & 31, ty = tid >> 5;
        #pragma unroll
        for (int i = 0; i < 32; i += 8)
            tile[ty + i][tx] = src[(size_t)(k0 + ty + i) * N + n0 + tx];
        __syncthreads();
        #pragma unroll
        for (int i = 0; i < 32; i += 8)
            dst[(size_t)(n0 + ty + i) * kD + k0 + tx] = __float2half(tile[tx][ty + i]);
    } else {
        // ---------------- rk0 partial ----------------
        int local = blk - (kNbLn + kNbCw0 + kNbCw1);
        int chunk = local >> 2, colblk = local & 3;
        int col = colblk * 256 + tid;
        int d0 = chunk * (kD / kRkChunks);
        float s = 0.f;
        #pragma unroll
        for (int i = 0; i < kD / kRkChunks; i++)
            s += r[d0 + i] * Wr[(size_t)(d0 + i) * kD + col];
        g_rk0p[chunk * kD + col] = s;
    }
}

__global__ void rk0_reduce_kernel() {
    int col = blockIdx.x * 256 + threadIdx.x;
    float s = 0.f;
    #pragma unroll
    for (int c = 0; c < kRkChunks; c++) s += g_rk0p[c * kD + col];
    g_rk0[col] = s;
}

// ------------------------------ QKV GEMM (fp16 mma, cp.async + ldmatrix) -----
__global__ __launch_bounds__(256) void gemm_qkv_kernel(const float* __restrict__ rw) {
    __shared__ __half As[2][128][40];
    __shared__ __half Bs[2][128][40];
    int tid = threadIdx.x, lane = tid & 31, w = tid >> 5;
    int gid = lane >> 2, tig = lane & 3;
    int m0 = blockIdx.y * 128, n0 = blockIdx.x * 128;
    int wm = w >> 2, wn = w & 3;
    constexpr unsigned stageB = 128 * 40 * 2;
    unsigned a_base = smem_u32(&As[0][wm * 64 + (lane & 15)][(lane >> 4) * 8]);
    unsigned b_base = smem_u32(&Bs[0][wn * 32 + (lane & 7) + ((lane >> 4) << 3)][((lane >> 3) & 1) * 8]);
    int lr = tid >> 2, lc = (tid & 3) * 8;
    int lr2 = lr + 64;
    float acc[4][4][4] = {};

    cp_async16(smem_u32(&As[0][lr][lc]),  &g_xn_h[(size_t)(m0 + lr) * kD + lc]);
    cp_async16(smem_u32(&As[0][lr2][lc]), &g_xn_h[(size_t)(m0 + lr2) * kD + lc]);
    cp_async16(smem_u32(&Bs[0][lr][lc]),  &g_wqkv_t[(size_t)(n0 + lr) * kD + lc]);
    cp_async16(smem_u32(&Bs[0][lr2][lc]), &g_wqkv_t[(size_t)(n0 + lr2) * kD + lc]);
    CP_COMMIT();

    constexpr int NIT = kD / 32;
    for (int it = 0; it < NIT; it++) {
        if (it + 1 < NIT) {
            int st = (it + 1) & 1, k0 = (it + 1) * 32;
            cp_async16(smem_u32(&As[st][lr][lc]),  &g_xn_h[(size_t)(m0 + lr) * kD + k0 + lc]);
            cp_async16(smem_u32(&As[st][lr2][lc]), &g_xn_h[(size_t)(m0 + lr2) * kD + k0 + lc]);
            cp_async16(smem_u32(&Bs[st][lr][lc]),  &g_wqkv_t[(size_t)(n0 + lr) * kD + k0 + lc]);
            cp_async16(smem_u32(&Bs[st][lr2][lc]), &g_wqkv_t[(size_t)(n0 + lr2) * kD + k0 + lc]);
            CP_COMMIT();
            CP_WAIT(1);
        } else {
            CP_WAIT(0);
        }
        __syncthreads();
        unsigned soff = (it & 1) * stageB;
        #pragma unroll
        for (int kb = 0; kb < 32; kb += 16) {
            unsigned a[4][4], b[2][4];
            #pragma unroll
            for (int mi = 0; mi < 4; mi++)
                ldsm_x4(a[mi], a_base + soff + (mi * 16 * 40 + kb) * 2);
            #pragma unroll
            for (int p = 0; p < 2; p++)
                ldsm_x4(b[p], b_base + soff + (p * 16 * 40 + kb) * 2);
            #pragma unroll
            for (int mi = 0; mi < 4; mi++)
                #pragma unroll
                for (int p = 0; p < 2; p++) {
                    mma16816(acc[mi][2 * p],     a[mi], b[p]);
                    mma16816(acc[mi][2 * p + 1], a[mi], b[p] + 2);
                }
        }
        __syncthreads();
    }
    // epilogue: scatter to q/k/v (all coalesced __half2)
    #pragma unroll
    for (int mi = 0; mi < 4; mi++) {
        int r0e = m0 + wm * 64 + mi * 16 + gid, r1e = r0e + 8;
        int s0 = r0e >> 1, b0e = r0e & 1;
        int s1 = r1e >> 1, b1e = r1e & 1;
        #pragma unroll
        for (int ni = 0; ni < 4; ni++) {
            int c0 = n0 + wn * 32 + ni * 8 + tig * 2;
            int part = c0 >> 10, rem = c0 & 1023, hh = rem >> 6, d = rem & 63;
            size_t di0 = (((size_t)(b0e * kH + hh)) * kS + s0) * kDh + d;
            size_t di1 = (((size_t)(b1e * kH + hh)) * kS + s1) * kDh + d;
            float v00 = acc[mi][ni][0], v01 = acc[mi][ni][1];
            float v10 = acc[mi][ni][2], v11 = acc[mi][ni][3];
            if (part == 0) {
                float w0 = rw[rem], w1 = rw[rem + 1];
                *(__half2*)&g_q[di0] = __floats2half2_rn(v00 + w0, v01 + w1);
                *(__half2*)&g_q[di1] = __floats2half2_rn(v10 + w0, v11 + w1);
            } else if (part == 1) {
                *(__half2*)&g_k[di0] = __floats2half2_rn(v00, v01);
                *(__half2*)&g_k[di1] = __floats2half2_rn(v10, v11);
            } else {
                *(__half2*)&g_v[di0] = __floats2half2_rn(v00, v01);
                *(__half2*)&g_v[di1] = __floats2half2_rn(v10, v11);
            }
        }
    }
}

// ------------- Flash attention (fp16 mma, 128q, reg-Q/P, fused cbd) ----------
// Block: 256 thr = 8 warps, one (b,h), 128 query rows (16/warp), key tiles 64.
__global__ __launch_bounds__(256) void flash_kernel(const float* __restrict__ rw,
                                                    const float* __restrict__ rr) {
    __shared__ __half Ks[2][64][72];
    __shared__ __half Vs[2][64][72];       // natural [j][d]
    __shared__ float csm[132];             // [0..128]=row consts, [130]=C_h
    int b = blockIdx.z, h = blockIdx.y, i0 = blockIdx.x * 128;
    int tid = threadIdx.x, w = tid >> 5, lane = tid & 31;
    int gid = lane >> 2, tig = lane & 3;
    size_t base = ((size_t)(b * kH + h)) * kS * kDh;

    // ---- stage Q through the K buffer, capture fragments + cbd dots ---------
    __half* qstage = &Ks[0][0][0];
    #pragma unroll
    for (int t = 0; t < 4; t++) {
        int idx = tid + t * 256;
        int r = idx >> 3, c = (idx & 7) * 8;
        *(float4*)&qstage[r * 72 + c] = *(const float4*)&g_q[base + (size_t)(i0 + r) * kDh + c];
    }
    __syncthreads();
    unsigned qf[4][4];
    {
        unsigned qa = smem_u32(qstage + (w * 16 + (lane & 15)) * 72 + (lane >> 4) * 8);
        #pragma unroll
        for (int c4 = 0; c4 < 4; c4++) ldsm_x4(qf[c4], qa + c4 * 32);
    }
    // C_h = sum_d (rr - rw) * rk0   (warp 0)
    if (w == 0) {
        int hd = h * kDh + lane;
        float chs = (rr[hd] - rw[hd]) * g_rk0[hd]
                  + (rr[hd + 32] - rw[hd + 32]) * g_rk0[hd + 32];
        #pragma unroll
        for (int o = 16; o; o >>= 1) chs += __shfl_xor_sync(~0u, chs, o);
        if (lane == 0) csm[130] = chs;
    }
    // row dots: c_raw[r] = q_row . rk0  (pairs of threads per row, from qstage)
    {
        int rrow = tid >> 1, halfsel = (tid & 1) * 32;
        const __half* qr = qstage + rrow * 72 + halfsel;
        const float* rk = g_rk0 + h * kDh + halfsel;
        float p = 0.f;
        #pragma unroll
        for (int d = 0; d < 32; d++) p += __half2float(qr[d]) * rk[d];
        p += __shfl_xor_sync(~0u, p, 1);
        if ((tid & 1) == 0) csm[rrow] = p;
    }
    // boundary row i0+128 (from gmem)
    if (tid < 2) {
        int gi = i0 + 128;
        float p = 0.f;
        if (gi < kS) {
            const __half* qr = &g_q[base + (size_t)gi * kDh + tid * 32];
            const float* rk = g_rk0 + h * kDh + tid * 32;
            #pragma unroll
            for (int d = 0; d < 32; d++) p += __half2float(qr[d]) * rk[d];
        }
        p += __shfl_xor_sync(0x3u, p, 1);
        if (tid == 0) csm[128] = p;
    }
    __syncthreads();   // Q captured + csm ready; K buffer reusable

    float Ch = csm[130];
    int lr0 = w * 16 + gid;
    int r0 = i0 + lr0, r1 = r0 + 8;
    float cA  = csm[lr0] + Ch;
    float cA1 = (r0 + 1 < kS) ? csm[lr0 + 1] + Ch : 0.f;
    float cB  = csm[lr0 + 8] + Ch;
    float cB1 = (r1 + 1 < kS) ? csm[lr0 + 9] + Ch : 0.f;

    unsigned ka_base = smem_u32(&Ks[0][(lane & 7) + ((lane >> 4) << 3)][((lane >> 3) & 1) * 8]);
    unsigned va_base = smem_u32(&Vs[0][(lane & 7) + (((lane >> 3) & 1) << 3)][(lane >> 4) * 8]);
    constexpr unsigned stageB = 64 * 72 * 2;

    float m0v = -1e30f, m1v = -1e30f, l0 = 0.f, l1 = 0.f;
    float o[8][4] = {};

    int plr = tid >> 2, plc = (tid & 3) * 8;
    cp_async16(smem_u32(&Ks[0][plr][plc]),      &g_k[base + (size_t)plr * kDh + plc]);
    cp_async16(smem_u32(&Ks[0][plr][plc + 32]), &g_k[base + (size_t)plr * kDh + plc + 32]);
    cp_async16(smem_u32(&Vs[0][plr][plc]),      &g_v[base + (size_t)plr * kDh + plc]);
    cp_async16(smem_u32(&Vs[0][plr][plc + 32]), &g_v[base + (size_t)plr * kDh + plc + 32]);
    CP_COMMIT();

    constexpr int NT = kS / 64;
    for (int jt = 0; jt < NT; jt++) {
        if (jt + 1 < NT) {
            int st = (jt + 1) & 1;
            size_t roff = base + (size_t)((jt + 1) * 64 + plr) * kDh + plc;
            cp_async16(smem_u32(&Ks[st][plr][plc]),      &g_k[roff]);
            cp_async16(smem_u32(&Ks[st][plr][plc + 32]), &g_k[roff + 32]);
            cp_async16(smem_u32(&Vs[st][plr][plc]),      &g_v[roff]);
            cp_async16(smem_u32(&Vs[st][plr][plc + 32]), &g_v[roff + 32]);
            CP_COMMIT();
            CP_WAIT(1);
        } else {
            CP_WAIT(0);
        }
        __syncthreads();
        unsigned soff = (jt & 1) * stageB;
        int j0 = jt * 64;

        // S = Q K^T  (per warp: 16 x 64)
        float s[8][4] = {};
        #pragma unroll
        for (int c4 = 0; c4 < 4; c4++) {
            #pragma unroll
            for (int p = 0; p < 4; p++) {
                unsigned bb[4];
                ldsm_x4(bb, ka_base + soff + (p * 16 * 72 + c4 * 16) * 2);
                mma16816(s[2 * p],     qf[c4], bb);
                mma16816(s[2 * p + 1], qf[c4], bb + 2);
            }
        }

        // BD + scale + online softmax (fp32), P packed to registers
        float rmax0 = -1e30f, rmax1 = -1e30f;
        #pragma unroll
        for (int nt = 0; nt < 8; nt++) {
            int gj = j0 + nt * 8 + tig * 2;
            float bd00 = (gj <= r0) ? cA : ((gj == r0 + 1) ? 0.f : cA1);
            float bd01 = (gj + 1 <= r0) ? cA : ((gj + 1 == r0 + 1) ? 0.f : cA1);
            float bd10 = (gj <= r1) ? cB : ((gj == r1 + 1) ? 0.f : cB1);
            float bd11 = (gj + 1 <= r1) ? cB : ((gj + 1 == r1 + 1) ? 0.f : cB1);
            s[nt][0] = (s[nt][0] + bd00) * kScale;
            s[nt][1] = (s[nt][1] + bd01) * kScale;
            s[nt][2] = (s[nt][2] + bd10) * kScale;
            s[nt][3] = (s[nt][3] + bd11) * kScale;
            rmax0 = fmaxf(rmax0, fmaxf(s[nt][0], s[nt][1]));
            rmax1 = fmaxf(rmax1, fmaxf(s[nt][2], s[nt][3]));
        }
        rmax0 = fmaxf(rmax0, __shfl_xor_sync(~0u, rmax0, 1));
        rmax0 = fmaxf(rmax0, __shfl_xor_sync(~0u, rmax0, 2));
        rmax1 = fmaxf(rmax1, __shfl_xor_sync(~0u, rmax1, 1));
        rmax1 = fmaxf(rmax1, __shfl_xor_sync(~0u, rmax1, 2));
        float mn0 = fmaxf(m0v, rmax0), mn1 = fmaxf(m1v, rmax1);
        float al0 = __expf(m0v - mn0), al1 = __expf(m1v - mn1);
        float rs0 = 0.f, rs1 = 0.f;
        unsigned ph0[8], ph1[8];
        #pragma unroll
        for (int nt = 0; nt < 8; nt++) {
            float p0 = __expf(s[nt][0] - mn0), p1 = __expf(s[nt][1] - mn0);
            float p2 = __expf(s[nt][2] - mn1), p3 = __expf(s[nt][3] - mn1);
            rs0 += p0 + p1; rs1 += p2 + p3;
            __half2 t0 = __floats2half2_rn(p0, p1);
            __half2 t1 = __floats2half2_rn(p2, p3);
            ph0[nt] = *(unsigned*)&t0;
            ph1[nt] = *(unsigned*)&t1;
        }
        rs0 += __shfl_xor_sync(~0u, rs0, 1);
        rs0 += __shfl_xor_sync(~0u, rs0, 2);
        rs1 += __shfl_xor_sync(~0u, rs1, 1);
        rs1 += __shfl_xor_sync(~0u, rs1, 2);
        l0 = l0 * al0 + rs0; l1 = l1 * al1 + rs1;
        m0v = mn0; m1v = mn1;
        #pragma unroll
        for (int nt = 0; nt < 8; nt++) {
            o[nt][0] *= al0; o[nt][1] *= al0;
            o[nt][2] *= al1; o[nt][3] *= al1;
        }

        // O += P V   (A from regs; B via ldmatrix.trans on natural V[j][d])
        #pragma unroll
        for (int c4 = 0; c4 < 4; c4++) {
            unsigned a[4] = { ph0[2 * c4], ph1[2 * c4], ph0[2 * c4 + 1], ph1[2 * c4 + 1] };
            #pragma unroll
            for (int p = 0; p < 4; p++) {
                unsigned bb[4];
                ldsm_x4_trans(bb, va_base + soff + (c4 * 16 * 72 + p * 16) * 2);
                mma16816(o[2 * p],     a, bb);
                mma16816(o[2 * p + 1], a, bb + 2);
            }
        }
        __syncthreads();
    }

    float inv0 = 1.f / l0, inv1 = 1.f / l1;
    #pragma unroll
    for (int nt = 0; nt < 8; nt++) {
        int d = nt * 8 + tig * 2;
        *(__half2*)&g_av[((size_t)r0 * kB + b) * kD + h * kDh + d] =
            __floats2half2_rn(o[nt][0] * inv0, o[nt][1] * inv0);
        *(__half2*)&g_av[((size_t)r1 * kB + b) * kD + h * kDh + d] =
            __floats2half2_rn(o[nt][2] * inv1, o[nt][3] * inv1);
    }
}

// ---------------------- Output GEMM + residual (fp16 mma) --------------------
__global__ __launch_bounds__(256) void gemm_out_kernel(float* __restrict__ out) {
    __shared__ __half As[2][128][40];
    __shared__ __half Bs[2][128][40];
    int tid = threadIdx.x, lane = tid & 31, w = tid >> 5;
    int gid = lane >> 2, tig = lane & 3;
    int m0 = blockIdx.y * 128, n0 = blockIdx.x * 128;
    int wm = w >> 2, wn = w & 3;
    constexpr unsigned stageB = 128 * 40 * 2;
    unsigned a_base = smem_u32(&As[0][wm * 64 + (lane & 15)][(lane >> 4) * 8]);
    unsigned b_base = smem_u32(&Bs[0][wn * 32 + (lane & 7) + ((lane >> 4) << 3)][((lane >> 3) & 1) * 8]);
    int lr = tid >> 2, lc = (tid & 3) * 8;
    int lr2 = lr + 64;
    float acc[4][4][4] = {};

    cp_async16(smem_u32(&As[0][lr][lc]),  &g_av[(size_t)(m0 + lr) * kD + lc]);
    cp_async16(smem_u32(&As[0][lr2][lc]), &g_av[(size_t)(m0 + lr2) * kD + lc]);
    cp_async16(smem_u32(&Bs[0][lr][lc]),  &g_wo_t[(size_t)(n0 + lr) * kD + lc]);
    cp_async16(smem_u32(&Bs[0][lr2][lc]), &g_wo_t[(size_t)(n0 + lr2) * kD + lc]);
    CP_COMMIT();

    constexpr int NIT = kD / 32;
    for (int it = 0; it < NIT; it++) {
        if (it + 1 < NIT) {
            int st = (it + 1) & 1, k0 = (it + 1) * 32;
            cp_async16(smem_u32(&As[st][lr][lc]),  &g_av[(size_t)(m0 + lr) * kD + k0 + lc]);
            cp_async16(smem_u32(&As[st][lr2][lc]), &g_av[(size_t)(m0 + lr2) * kD + k0 + lc]);
            cp_async16(smem_u32(&Bs[st][lr][lc]),  &g_wo_t[(size_t)(n0 + lr) * kD + k0 + lc]);
            cp_async16(smem_u32(&Bs[st][lr2][lc]), &g_wo_t[(size_t)(n0 + lr2) * kD + k0 + lc]);
            CP_COMMIT();
            CP_WAIT(1);
        } else {
            CP_WAIT(0);
        }
        __syncthreads();
        unsigned soff = (it & 1) * stageB;
        #pragma unroll
        for (int kb = 0; kb < 32; kb += 16) {
            unsigned a[4][4], b[2][4];
            #pragma unroll
            for (int mi = 0; mi < 4; mi++)
                ldsm_x4(a[mi], a_base + soff + (mi * 16 * 40 + kb) * 2);
            #pragma unroll
            for (int p = 0; p < 2; p++)
                ldsm_x4(b[p], b_base + soff + (p * 16 * 40 + kb) * 2);
            #pragma unroll
            for (int mi = 0; mi < 4; mi++)
                #pragma unroll
                for (int p = 0; p < 2; p++) {
                    mma16816(acc[mi][2 * p],     a[mi], b[p]);
                    mma16816(acc[mi][2 * p + 1], a[mi], b[p] + 2);
                }
        }
        __syncthreads();
    }
    #pragma unroll
    for (int mi = 0; mi < 4; mi++) {
        int r0e = m0 + wm * 64 + mi * 16 + gid, r1e = r0e + 8;
        #pragma unroll
        for (int ni = 0; ni < 4; ni++) {
            int c0 = n0 + wn * 32 + ni * 8 + tig * 2;
            float2 x0 = *(const float2*)&g_xn[(size_t)r0e * kD + c0];
            float2 x1 = *(const float2*)&g_xn[(size_t)r1e * kD + c0];
            float2 o0 = { acc[mi][ni][0] + x0.x, acc[mi][ni][1] + x0.y };
            float2 o1 = { acc[mi][ni][2] + x1.x, acc[mi][ni][3] + x1.y };
            *(float2*)&out[(size_t)r0e * kD + c0] = o0;
            *(float2*)&out[(size_t)r1e * kD + c0] = o1;
        }
    }
}

// --------------------------------- launch ------------------------------------
extern "C" void kernel_launch(void* const* d_in, const int* in_sizes, int n_in,
                              void* d_out, int out_size) {
    const float* x    = (const float*)d_in[0];
    const float* r    = (const float*)d_in[1];
    const float* rw   = (const float*)d_in[2];
    const float* rr   = (const float*)d_in[3];
    const float* ln_g = (const float*)d_in[4];
    const float* ln_b = (const float*)d_in[5];
    const float* Wqkv = (const float*)d_in[6];
    const float* Wr   = (const float*)d_in[7];
    const float* Wo   = (const float*)d_in[8];
    float* out = (float*)d_out;

    prologue_kernel<<<kNbLn + kNbCw0 + kNbCw1 + kNbRk, 256>>>(x, ln_g, ln_b, Wqkv, Wo, r, Wr);
    rk0_reduce_kernel<<<kD / 256, 256>>>();
    gemm_qkv_kernel<<<dim3(3 * kD / 128, kRows / 128), 256>>>(rw);
    flash_kernel<<<dim3(kS / 128, kH, kB), 256>>>(rw, rr);
    gemm_out_kernel<<<dim3(kD / 128, kRows / 128), 256>>>(out);
}

// round 14
// speedup vs baseline: 6.5261x; 1.0210x over previous
#include <cuda_runtime.h>
#include <cuda_fp16.h>
#include <math.h>

namespace {
constexpr int kS = 2048, kB = 2, kD = 1024, kH = 16, kDh = 64;
constexpr int kRows = kS * kB;            // 4096
constexpr float kScale = 0.125f;          // 1/sqrt(64)
constexpr float kEps = 1e-5f;
constexpr int kRkChunks = 16;
// prologue block ranges
constexpr int kNbLn  = kRows;                       // 4096
constexpr int kNbCw0 = (3 * kD / 32) * (kD / 32);   // 3072
constexpr int kNbCw1 = (kD / 32) * (kD / 32);       // 1024
constexpr int kNbRk  = (kD / 256) * kRkChunks;      // 64
}

// ------------------------- scratch (static device memory) -------------------
// NOTE: only referenced inside device code — never passed as kernel args.
__device__ float  g_xn[kRows * kD];
__device__ __half g_xn_h[kRows * kD];
__device__ __half g_wqkv_t[3 * kD * kD];           // Wqkv^T [n][k]
__device__ __half g_wo_t[kD * kD];                 // Wo^T [n][k]
__device__ __half g_q[kB * kH * kS * kDh];         // q + rw [b][h][s][d]
__device__ __half g_k[kB * kH * kS * kDh];         // [b][h][s][d]
__device__ __half g_v[kB * kH * kS * kDh];         // [b][h][s][d]
__device__ __half g_av[kRows * kD];
__device__ float  g_rk0p[kRkChunks * kD];
__device__ float  g_rk0[kD];

// ------------------------------ asm helpers ----------------------------------
__device__ __forceinline__ void mma16816(float* c, const unsigned* a, const unsigned* b) {
    asm volatile(
        "mma.sync.aligned.m16n8k16.row.col.f32.f16.f16.f32 "
        "{%0,%1,%2,%3},{%4,%5,%6,%7},{%8,%9},{%0,%1,%2,%3};\n"
        : "+f"(c[0]), "+f"(c[1]), "+f"(c[2]), "+f"(c[3])
        : "r"(a[0]), "r"(a[1]), "r"(a[2]), "r"(a[3]), "r"(b[0]), "r"(b[1]));
}
__device__ __forceinline__ void ldsm_x4(unsigned* r, unsigned addr) {
    asm volatile("ldmatrix.sync.aligned.m8n8.x4.shared.b16 {%0,%1,%2,%3}, [%4];\n"
                 : "=r"(r[0]), "=r"(r[1]), "=r"(r[2]), "=r"(r[3]) : "r"(addr));
}
__device__ __forceinline__ void ldsm_x4_trans(unsigned* r, unsigned addr) {
    asm volatile("ldmatrix.sync.aligned.m8n8.x4.trans.shared.b16 {%0,%1,%2,%3}, [%4];\n"
                 : "=r"(r[0]), "=r"(r[1]), "=r"(r[2]), "=r"(r[3]) : "r"(addr));
}
__device__ __forceinline__ unsigned smem_u32(const void* p) {
    return (unsigned)__cvta_generic_to_shared(p);
}
__device__ __forceinline__ void cp_async16(unsigned dst, const void* src) {
    asm volatile("cp.async.cg.shared.global [%0], [%1], 16;\n"
                 :: "r"(dst), "l"(__cvta_generic_to_global(src)));
}
#define CP_COMMIT() asm volatile("cp.async.commit_group;\n")
#define CP_WAIT(n)  asm volatile("cp.async.wait_group %0;\n" :: "n"(n))

// ------------------- fused prologue: ln | convw0 | convw1 | rk0_part ---------
__global__ __launch_bounds__(256) void prologue_kernel(
        const float* __restrict__ x, const float* __restrict__ gamma,
        const float* __restrict__ beta, const float* __restrict__ Wqkv,
        const float* __restrict__ Wo, const float* __restrict__ r,
        const float* __restrict__ Wr) {
    __shared__ float tile[32][33];
    __shared__ float sm1[8], sm2[8];
    int blk = blockIdx.x;
    int tid = threadIdx.x;

    if (blk < kNbLn) {
        // ---------------- LayerNorm ----------------
        int row = blk, t = tid;
        const float4 v = reinterpret_cast<const float4*>(x + (size_t)row * kD)[t];
        float s1 = v.x + v.y + v.z + v.w;
        float s2 = v.x*v.x + v.y*v.y + v.z*v.z + v.w*v.w;
        #pragma unroll
        for (int o = 16; o; o >>= 1) {
            s1 += __shfl_xor_sync(~0u, s1, o);
            s2 += __shfl_xor_sync(~0u, s2, o);
        }
        int w = t >> 5, lane = t & 31;
        if (lane == 0) { sm1[w] = s1; sm2[w] = s2; }
        __syncthreads();
        if (w == 0) {
            s1 = (lane < 8) ? sm1[lane] : 0.f;
            s2 = (lane < 8) ? sm2[lane] : 0.f;
            #pragma unroll
            for (int o = 4; o; o >>= 1) {
                s1 += __shfl_xor_sync(~0u, s1, o);
                s2 += __shfl_xor_sync(~0u, s2, o);
            }
            if (lane == 0) { sm1[0] = s1; sm2[0] = s2; }
        }
        __syncthreads();
        float mu = sm1[0] * (1.f / kD);
        float var = sm2[0] * (1.f / kD) - mu * mu;
        float rstd = rsqrtf(var + kEps);
        const float4 gv = reinterpret_cast<const float4*>(gamma)[t];
        const float4 bv = reinterpret_cast<const float4*>(beta)[t];
        float4 o;
        o.x = (v.x - mu) * rstd * gv.x + bv.x;
        o.y = (v.y - mu) * rstd * gv.y + bv.y;
        o.z = (v.z - mu) * rstd * gv.z + bv.z;
        o.w = (v.w - mu) * rstd * gv.w + bv.w;
        reinterpret_cast<float4*>(g_xn + (size_t)row * kD)[t] = o;
        *reinterpret_cast<__half2*>(&g_xn_h[(size_t)row * kD + t * 4])     = __floats2half2_rn(o.x, o.y);
        *reinterpret_cast<__half2*>(&g_xn_h[(size_t)row * kD + t * 4 + 2]) = __floats2half2_rn(o.z, o.w);
    } else if (blk < kNbLn + kNbCw0 + kNbCw1) {
        // ---------------- weight transpose + cast ----------------
        bool first = (blk < kNbLn + kNbCw0);
        int local = first ? (blk - kNbLn) : (blk - kNbLn - kNbCw0);
        int N = first ? 3 * kD : kD;
        const float* src = first ? Wqkv : Wo;
        __half* dst = first ? g_wqkv_t : g_wo_t;
        int nt = N / 32;
        int bx = local % nt, by = local / nt;
        int n0 = bx * 32, k0 = by * 32;
        int tx = tid & 31, ty = tid >> 5;
        #pragma unroll
        for (int i = 0; i < 32; i += 8)
            tile[ty + i][tx] = src[(size_t)(k0 + ty + i) * N + n0 + tx];
        __syncthreads();
        #pragma unroll
        for (int i = 0; i < 32; i += 8)
            dst[(size_t)(n0 + ty + i) * kD + k0 + tx] = __float2half(tile[tx][ty + i]);
    } else {
        // ---------------- rk0 partial ----------------
        int local = blk - (kNbLn + kNbCw0 + kNbCw1);
        int chunk = local >> 2, colblk = local & 3;
        int col = colblk * 256 + tid;
        int d0 = chunk * (kD / kRkChunks);
        float s = 0.f;
        #pragma unroll
        for (int i = 0; i < kD / kRkChunks; i++)
            s += r[d0 + i] * Wr[(size_t)(d0 + i) * kD + col];
        g_rk0p[chunk * kD + col] = s;
    }
}

__global__ void rk0_reduce_kernel() {
    int col = blockIdx.x * 256 + threadIdx.x;
    float s = 0.f;
    #pragma unroll
    for (int c = 0; c < kRkChunks; c++) s += g_rk0p[c * kD + col];
    g_rk0[col] = s;
}

// ------------------------------ QKV GEMM (fp16 mma, cp.async + ldmatrix) -----
__global__ __launch_bounds__(256) void gemm_qkv_kernel(const float* __restrict__ rw) {
    __shared__ __half As[2][128][40];
    __shared__ __half Bs[2][128][40];
    int tid = threadIdx.x, lane = tid & 31, w = tid >> 5;
    int gid = lane >> 2, tig = lane & 3;
    int m0 = blockIdx.y * 128, n0 = blockIdx.x * 128;
    int wm = w >> 2, wn = w & 3;
    constexpr unsigned stageB = 128 * 40 * 2;
    unsigned a_base = smem_u32(&As[0][wm * 64 + (lane & 15)][(lane >> 4) * 8]);
    unsigned b_base = smem_u32(&Bs[0][wn * 32 + (lane & 7) + ((lane >> 4) << 3)][((lane >> 3) & 1) * 8]);
    int lr = tid >> 2, lc = (tid & 3) * 8;
    int lr2 = lr + 64;
    float acc[4][4][4] = {};

    cp_async16(smem_u32(&As[0][lr][lc]),  &g_xn_h[(size_t)(m0 + lr) * kD + lc]);
    cp_async16(smem_u32(&As[0][lr2][lc]), &g_xn_h[(size_t)(m0 + lr2) * kD + lc]);
    cp_async16(smem_u32(&Bs[0][lr][lc]),  &g_wqkv_t[(size_t)(n0 + lr) * kD + lc]);
    cp_async16(smem_u32(&Bs[0][lr2][lc]), &g_wqkv_t[(size_t)(n0 + lr2) * kD + lc]);
    CP_COMMIT();

    constexpr int NIT = kD / 32;
    for (int it = 0; it < NIT; it++) {
        if (it + 1 < NIT) {
            int st = (it + 1) & 1, k0 = (it + 1) * 32;
            cp_async16(smem_u32(&As[st][lr][lc]),  &g_xn_h[(size_t)(m0 + lr) * kD + k0 + lc]);
            cp_async16(smem_u32(&As[st][lr2][lc]), &g_xn_h[(size_t)(m0 + lr2) * kD + k0 + lc]);
            cp_async16(smem_u32(&Bs[st][lr][lc]),  &g_wqkv_t[(size_t)(n0 + lr) * kD + k0 + lc]);
            cp_async16(smem_u32(&Bs[st][lr2][lc]), &g_wqkv_t[(size_t)(n0 + lr2) * kD + k0 + lc]);
            CP_COMMIT();
            CP_WAIT(1);
        } else {
            CP_WAIT(0);
        }
        __syncthreads();
        unsigned soff = (it & 1) * stageB;
        #pragma unroll
        for (int kb = 0; kb < 32; kb += 16) {
            unsigned a[4][4], b[2][4];
            #pragma unroll
            for (int mi = 0; mi < 4; mi++)
                ldsm_x4(a[mi], a_base + soff + (mi * 16 * 40 + kb) * 2);
            #pragma unroll
            for (int p = 0; p < 2; p++)
                ldsm_x4(b[p], b_base + soff + (p * 16 * 40 + kb) * 2);
            #pragma unroll
            for (int mi = 0; mi < 4; mi++)
                #pragma unroll
                for (int p = 0; p < 2; p++) {
                    mma16816(acc[mi][2 * p],     a[mi], b[p]);
                    mma16816(acc[mi][2 * p + 1], a[mi], b[p] + 2);
                }
        }
        __syncthreads();
    }
    // epilogue: scatter to q/k/v (all coalesced __half2)
    #pragma unroll
    for (int mi = 0; mi < 4; mi++) {
        int r0e = m0 + wm * 64 + mi * 16 + gid, r1e = r0e + 8;
        int s0 = r0e >> 1, b0e = r0e & 1;
        int s1 = r1e >> 1, b1e = r1e & 1;
        #pragma unroll
        for (int ni = 0; ni < 4; ni++) {
            int c0 = n0 + wn * 32 + ni * 8 + tig * 2;
            int part = c0 >> 10, rem = c0 & 1023, hh = rem >> 6, d = rem & 63;
            size_t di0 = (((size_t)(b0e * kH + hh)) * kS + s0) * kDh + d;
            size_t di1 = (((size_t)(b1e * kH + hh)) * kS + s1) * kDh + d;
            float v00 = acc[mi][ni][0], v01 = acc[mi][ni][1];
            float v10 = acc[mi][ni][2], v11 = acc[mi][ni][3];
            if (part == 0) {
                float w0 = rw[rem], w1 = rw[rem + 1];
                *(__half2*)&g_q[di0] = __floats2half2_rn(v00 + w0, v01 + w1);
                *(__half2*)&g_q[di1] = __floats2half2_rn(v10 + w0, v11 + w1);
            } else if (part == 1) {
                *(__half2*)&g_k[di0] = __floats2half2_rn(v00, v01);
                *(__half2*)&g_k[di1] = __floats2half2_rn(v10, v11);
            } else {
                *(__half2*)&g_v[di0] = __floats2half2_rn(v00, v01);
                *(__half2*)&g_v[di1] = __floats2half2_rn(v10, v11);
            }
        }
    }
}

// ------------- Flash attention (fp16 mma, 128q, reg-Q/P, fused cbd) ----------
// Block: 256 thr = 8 warps, one (b,h), 128 query rows (16/warp), key tiles 64.
__global__ __launch_bounds__(256) void flash_kernel(const float* __restrict__ rw,
                                                    const float* __restrict__ rr) {
    __shared__ __half Ks[2][64][72];
    __shared__ __half Vs[2][64][72];       // natural [j][d]
    __shared__ float csm[132];             // [0..128]=row consts, [130]=C_h
    int b = blockIdx.z, h = blockIdx.y, i0 = blockIdx.x * 128;
    int tid = threadIdx.x, w = tid >> 5, lane = tid & 31;
    int gid = lane >> 2, tig = lane & 3;
    size_t base = ((size_t)(b * kH + h)) * kS * kDh;

    // ---- stage Q through the K buffer, capture fragments + cbd dots ---------
    __half* qstage = &Ks[0][0][0];
    #pragma unroll
    for (int t = 0; t < 4; t++) {
        int idx = tid + t * 256;
        int r = idx >> 3, c = (idx & 7) * 8;
        *(float4*)&qstage[r * 72 + c] = *(const float4*)&g_q[base + (size_t)(i0 + r) * kDh + c];
    }
    __syncthreads();
    unsigned qf[4][4];
    {
        unsigned qa = smem_u32(qstage + (w * 16 + (lane & 15)) * 72 + (lane >> 4) * 8);
        #pragma unroll
        for (int c4 = 0; c4 < 4; c4++) ldsm_x4(qf[c4], qa + c4 * 32);
    }
    // C_h = sum_d (rr - rw) * rk0   (warp 0)
    if (w == 0) {
        int hd = h * kDh + lane;
        float chs = (rr[hd] - rw[hd]) * g_rk0[hd]
                  + (rr[hd + 32] - rw[hd + 32]) * g_rk0[hd + 32];
        #pragma unroll
        for (int o = 16; o; o >>= 1) chs += __shfl_xor_sync(~0u, chs, o);
        if (lane == 0) csm[130] = chs;
    }
    // row dots: c_raw[r] = q_row . rk0  (pairs of threads per row, from qstage)
    {
        int rrow = tid >> 1, halfsel = (tid & 1) * 32;
        const __half* qr = qstage + rrow * 72 + halfsel;
        const float* rk = g_rk0 + h * kDh + halfsel;
        float p = 0.f;
        #pragma unroll
        for (int d = 0; d < 32; d++) p += __half2float(qr[d]) * rk[d];
        p += __shfl_xor_sync(~0u, p, 1);
        if ((tid & 1) == 0) csm[rrow] = p;
    }
    // boundary row i0+128 (from gmem)
    if (tid < 2) {
        int gi = i0 + 128;
        float p = 0.f;
        if (gi < kS) {
            const __half* qr = &g_q[base + (size_t)gi * kDh + tid * 32];
            const float* rk = g_rk0 + h * kDh + tid * 32;
            #pragma unroll
            for (int d = 0; d < 32; d++) p += __half2float(qr[d]) * rk[d];
        }
        p += __shfl_xor_sync(0x3u, p, 1);
        if (tid == 0) csm[128] = p;
    }
    __syncthreads();   // Q captured + csm ready; K buffer reusable

    float Ch = csm[130];
    int lr0 = w * 16 + gid;
    int r0 = i0 + lr0, r1 = r0 + 8;
    float cA  = csm[lr0] + Ch;
    float cA1 = (r0 + 1 < kS) ? csm[lr0 + 1] + Ch : 0.f;
    float cB  = csm[lr0 + 8] + Ch;
    float cB1 = (r1 + 1 < kS) ? csm[lr0 + 9] + Ch : 0.f;

    unsigned ka_base = smem_u32(&Ks[0][(lane & 7) + ((lane >> 4) << 3)][((lane >> 3) & 1) * 8]);
    unsigned va_base = smem_u32(&Vs[0][(lane & 7) + (((lane >> 3) & 1) << 3)][(lane >> 4) * 8]);
    constexpr unsigned stageB = 64 * 72 * 2;

    float m0v = -1e30f, m1v = -1e30f, l0 = 0.f, l1 = 0.f;
    float o[8][4] = {};

    int plr = tid >> 2, plc = (tid & 3) * 8;
    cp_async16(smem_u32(&Ks[0][plr][plc]),      &g_k[base + (size_t)plr * kDh + plc]);
    cp_async16(smem_u32(&Ks[0][plr][plc + 32]), &g_k[base + (size_t)plr * kDh + plc + 32]);
    cp_async16(smem_u32(&Vs[0][plr][plc]),      &g_v[base + (size_t)plr * kDh + plc]);
    cp_async16(smem_u32(&Vs[0][plr][plc + 32]), &g_v[base + (size_t)plr * kDh + plc + 32]);
    CP_COMMIT();

    constexpr int NT = kS / 64;
    for (int jt = 0; jt < NT; jt++) {
        if (jt + 1 < NT) {
            int st = (jt + 1) & 1;
            size_t roff = base + (size_t)((jt + 1) * 64 + plr) * kDh + plc;
            cp_async16(smem_u32(&Ks[st][plr][plc]),      &g_k[roff]);
            cp_async16(smem_u32(&Ks[st][plr][plc + 32]), &g_k[roff + 32]);
            cp_async16(smem_u32(&Vs[st][plr][plc]),      &g_v[roff]);
            cp_async16(smem_u32(&Vs[st][plr][plc + 32]), &g_v[roff + 32]);
            CP_COMMIT();
            CP_WAIT(1);
        } else {
            CP_WAIT(0);
        }
        __syncthreads();
        unsigned soff = (jt & 1) * stageB;
        int j0 = jt * 64;

        // S = Q K^T  (per warp: 16 x 64)
        float s[8][4] = {};
        #pragma unroll
        for (int c4 = 0; c4 < 4; c4++) {
            #pragma unroll
            for (int p = 0; p < 4; p++) {
                unsigned bb[4];
                ldsm_x4(bb, ka_base + soff + (p * 16 * 72 + c4 * 16) * 2);
                mma16816(s[2 * p],     qf[c4], bb);
                mma16816(s[2 * p + 1], qf[c4], bb + 2);
            }
        }

        // BD + scale: warp-uniform fast paths (tile fully before/after diagonal)
        float rmax0 = -1e30f, rmax1 = -1e30f;
        bool allA  = (j0 + 63) <= (i0 + w * 16);       // all gj <= r0 for every row
        bool allA1 = j0 >= (i0 + w * 16 + 17);         // all gj >= r1+2 for every row
        if (allA | allA1) {
            float b0 = allA ? cA : cA1;
            float b1 = allA ? cB : cB1;
            #pragma unroll
            for (int nt = 0; nt < 8; nt++) {
                s[nt][0] = (s[nt][0] + b0) * kScale;
                s[nt][1] = (s[nt][1] + b0) * kScale;
                s[nt][2] = (s[nt][2] + b1) * kScale;
                s[nt][3] = (s[nt][3] + b1) * kScale;
                rmax0 = fmaxf(rmax0, fmaxf(s[nt][0], s[nt][1]));
                rmax1 = fmaxf(rmax1, fmaxf(s[nt][2], s[nt][3]));
            }
        } else {
            #pragma unroll
            for (int nt = 0; nt < 8; nt++) {
                int gj = j0 + nt * 8 + tig * 2;
                float bd00 = (gj <= r0) ? cA : ((gj == r0 + 1) ? 0.f : cA1);
                float bd01 = (gj + 1 <= r0) ? cA : ((gj + 1 == r0 + 1) ? 0.f : cA1);
                float bd10 = (gj <= r1) ? cB : ((gj == r1 + 1) ? 0.f : cB1);
                float bd11 = (gj + 1 <= r1) ? cB : ((gj + 1 == r1 + 1) ? 0.f : cB1);
                s[nt][0] = (s[nt][0] + bd00) * kScale;
                s[nt][1] = (s[nt][1] + bd01) * kScale;
                s[nt][2] = (s[nt][2] + bd10) * kScale;
                s[nt][3] = (s[nt][3] + bd11) * kScale;
                rmax0 = fmaxf(rmax0, fmaxf(s[nt][0], s[nt][1]));
                rmax1 = fmaxf(rmax1, fmaxf(s[nt][2], s[nt][3]));
            }
        }
        rmax0 = fmaxf(rmax0, __shfl_xor_sync(~0u, rmax0, 1));
        rmax0 = fmaxf(rmax0, __shfl_xor_sync(~0u, rmax0, 2));
        rmax1 = fmaxf(rmax1, __shfl_xor_sync(~0u, rmax1, 1));
        rmax1 = fmaxf(rmax1, __shfl_xor_sync(~0u, rmax1, 2));
        float mn0 = fmaxf(m0v, rmax0), mn1 = fmaxf(m1v, rmax1);
        float al0 = __expf(m0v - mn0), al1 = __expf(m1v - mn1);
        float rs0 = 0.f, rs1 = 0.f;
        unsigned ph0[8], ph1[8];
        #pragma unroll
        for (int nt = 0; nt < 8; nt++) {
            float p0 = __expf(s[nt][0] - mn0), p1 = __expf(s[nt][1] - mn0);
            float p2 = __expf(s[nt][2] - mn1), p3 = __expf(s[nt][3] - mn1);
            rs0 += p0 + p1; rs1 += p2 + p3;
            __half2 t0 = __floats2half2_rn(p0, p1);
            __half2 t1 = __floats2half2_rn(p2, p3);
            ph0[nt] = *(unsigned*)&t0;
            ph1[nt] = *(unsigned*)&t1;
        }
        rs0 += __shfl_xor_sync(~0u, rs0, 1);
        rs0 += __shfl_xor_sync(~0u, rs0, 2);
        rs1 += __shfl_xor_sync(~0u, rs1, 1);
        rs1 += __shfl_xor_sync(~0u, rs1, 2);
        l0 = l0 * al0 + rs0; l1 = l1 * al1 + rs1;
        m0v = mn0; m1v = mn1;
        #pragma unroll
        for (int nt = 0; nt < 8; nt++) {
            o[nt][0] *= al0; o[nt][1] *= al0;
            o[nt][2] *= al1; o[nt][3] *= al1;
        }

        // O += P V   (A from regs; B via ldmatrix.trans on natural V[j][d])
        #pragma unroll
        for (int c4 = 0; c4 < 4; c4++) {
            unsigned a[4] = { ph0[2 * c4], ph1[2 * c4], ph0[2 * c4 + 1], ph1[2 * c4 + 1] };
            #pragma unroll
            for (int p = 0; p < 4; p++) {
                unsigned bb[4];
                ldsm_x4_trans(bb, va_base + soff + (c4 * 16 * 72 + p * 16) * 2);
                mma16816(o[2 * p],     a, bb);
                mma16816(o[2 * p + 1], a, bb + 2);
            }
        }
        __syncthreads();
    }

    float inv0 = 1.f / l0, inv1 = 1.f / l1;
    #pragma unroll
    for (int nt = 0; nt < 8; nt++) {
        int d = nt * 8 + tig * 2;
        *(__half2*)&g_av[((size_t)r0 * kB + b) * kD + h * kDh + d] =
            __floats2half2_rn(o[nt][0] * inv0, o[nt][1] * inv0);
        *(__half2*)&g_av[((size_t)r1 * kB + b) * kD + h * kDh + d] =
            __floats2half2_rn(o[nt][2] * inv1, o[nt][3] * inv1);
    }
}

// ---------------------- Output GEMM + residual (fp16 mma) --------------------
__global__ __launch_bounds__(256) void gemm_out_kernel(float* __restrict__ out) {
    __shared__ __half As[2][128][40];
    __shared__ __half Bs[2][128][40];
    int tid = threadIdx.x, lane = tid & 31, w = tid >> 5;
    int gid = lane >> 2, tig = lane & 3;
    int m0 = blockIdx.y * 128, n0 = blockIdx.x * 128;
    int wm = w >> 2, wn = w & 3;
    constexpr unsigned stageB = 128 * 40 * 2;
    unsigned a_base = smem_u32(&As[0][wm * 64 + (lane & 15)][(lane >> 4) * 8]);
    unsigned b_base = smem_u32(&Bs[0][wn * 32 + (lane & 7) + ((lane >> 4) << 3)][((lane >> 3) & 1) * 8]);
    int lr = tid >> 2, lc = (tid & 3) * 8;
    int lr2 = lr + 64;
    float acc[4][4][4] = {};

    cp_async16(smem_u32(&As[0][lr][lc]),  &g_av[(size_t)(m0 + lr) * kD + lc]);
    cp_async16(smem_u32(&As[0][lr2][lc]), &g_av[(size_t)(m0 + lr2) * kD + lc]);
    cp_async16(smem_u32(&Bs[0][lr][lc]),  &g_wo_t[(size_t)(n0 + lr) * kD + lc]);
    cp_async16(smem_u32(&Bs[0][lr2][lc]), &g_wo_t[(size_t)(n0 + lr2) * kD + lc]);
    CP_COMMIT();

    constexpr int NIT = kD / 32;
    for (int it = 0; it < NIT; it++) {
        if (it + 1 < NIT) {
            int st = (it + 1) & 1, k0 = (it + 1) * 32;
            cp_async16(smem_u32(&As[st][lr][lc]),  &g_av[(size_t)(m0 + lr) * kD + k0 + lc]);
            cp_async16(smem_u32(&As[st][lr2][lc]), &g_av[(size_t)(m0 + lr2) * kD + k0 + lc]);
            cp_async16(smem_u32(&Bs[st][lr][lc]),  &g_wo_t[(size_t)(n0 + lr) * kD + k0 + lc]);
            cp_async16(smem_u32(&Bs[st][lr2][lc]), &g_wo_t[(size_t)(n0 + lr2) * kD + k0 + lc]);
            CP_COMMIT();
            CP_WAIT(1);
        } else {
            CP_WAIT(0);
        }
        __syncthreads();
        unsigned soff = (it & 1) * stageB;
        #pragma unroll
        for (int kb = 0; kb < 32; kb += 16) {
            unsigned a[4][4], b[2][4];
            #pragma unroll
            for (int mi = 0; mi < 4; mi++)
                ldsm_x4(a[mi], a_base + soff + (mi * 16 * 40 + kb) * 2);
            #pragma unroll
            for (int p = 0; p < 2; p++)
                ldsm_x4(b[p], b_base + soff + (p * 16 * 40 + kb) * 2);
            #pragma unroll
            for (int mi = 0; mi < 4; mi++)
                #pragma unroll
                for (int p = 0; p < 2; p++) {
                    mma16816(acc[mi][2 * p],     a[mi], b[p]);
                    mma16816(acc[mi][2 * p + 1], a[mi], b[p] + 2);
                }
        }
        __syncthreads();
    }
    #pragma unroll
    for (int mi = 0; mi < 4; mi++) {
        int r0e = m0 + wm * 64 + mi * 16 + gid, r1e = r0e + 8;
        #pragma unroll
        for (int ni = 0; ni < 4; ni++) {
            int c0 = n0 + wn * 32 + ni * 8 + tig * 2;
            float2 x0 = *(const float2*)&g_xn[(size_t)r0e * kD + c0];
            float2 x1 = *(const float2*)&g_xn[(size_t)r1e * kD + c0];
            float2 o0 = { acc[mi][ni][0] + x0.x, acc[mi][ni][1] + x0.y };
            float2 o1 = { acc[mi][ni][2] + x1.x, acc[mi][ni][3] + x1.y };
            *(float2*)&out[(size_t)r0e * kD + c0] = o0;
            *(float2*)&out[(size_t)r1e * kD + c0] = o1;
        }
    }
}

// --------------------------------- launch ------------------------------------
extern "C" void kernel_launch(void* const* d_in, const int* in_sizes, int n_in,
                              void* d_out, int out_size) {
    const float* x    = (const float*)d_in[0];
    const float* r    = (const float*)d_in[1];
    const float* rw   = (const float*)d_in[2];
    const float* rr   = (const float*)d_in[3];
    const float* ln_g = (const float*)d_in[4];
    const float* ln_b = (const float*)d_in[5];
    const float* Wqkv = (const float*)d_in[6];
    const float* Wr   = (const float*)d_in[7];
    const float* Wo   = (const float*)d_in[8];
    float* out = (float*)d_out;

    prologue_kernel<<<kNbLn + kNbCw0 + kNbCw1 + kNbRk, 256>>>(x, ln_g, ln_b, Wqkv, Wo, r, Wr);
    rk0_reduce_kernel<<<kD / 256, 256>>>();
    gemm_qkv_kernel<<<dim3(3 * kD / 128, kRows / 128), 256>>>(rw);
    flash_kernel<<<dim3(kS / 128, kH, kB), 256>>>(rw, rr);
    gemm_out_kernel<<<dim3(kD / 128, kRows / 128), 256>>>(out);
}